// round 7
// baseline (speedup 1.0000x reference)
#include <cuda_runtime.h>
#include <cuda_bf16.h>
#include <math.h>
#include <cstdint>

// Problem constants
#define B_ 2
#define S_ 2048
#define D_ 1024
#define H_ 16
#define DK_ 64

// ---------------------------------------------------------------------------
// Scratch (__device__ globals; no allocation allowed)
// ---------------------------------------------------------------------------
__device__ float g_v[B_ * S_ * D_];  // [B,H,S,64] f32 (pre-transpose V)
__device__ float2 g_sc[S_ * 32];

// bf16 split buffers
__device__ __nv_bfloat16 g_xh[B_ * S_ * D_];
__device__ __nv_bfloat16 g_xl[B_ * S_ * D_];
__device__ __nv_bfloat16 g_ah[B_ * S_ * D_];   // attn out hi [B,S,H,64]
__device__ __nv_bfloat16 g_al[B_ * S_ * D_];
__device__ __nv_bfloat16 g_wh[4][D_ * D_];
__device__ __nv_bfloat16 g_wl[4][D_ * D_];

__device__ __nv_bfloat16 g_qh[B_ * S_ * D_];   // [B,H,S,64], rope+scaled
__device__ __nv_bfloat16 g_ql[B_ * S_ * D_];
__device__ __nv_bfloat16 g_kh[B_ * S_ * D_];   // [B,H,S,64], rope
__device__ __nv_bfloat16 g_kl[B_ * S_ * D_];
__device__ __nv_bfloat16 g_vth[B_ * S_ * D_];  // [B,H,64,S]
__device__ __nv_bfloat16 g_vtl[B_ * S_ * D_];

// ---------------------------------------------------------------------------
// PTX helpers (baseline ISA: mma.sync / ldmatrix / cp.async — sm_103-safe)
// ---------------------------------------------------------------------------
__device__ __forceinline__ uint32_t smem_u32(const void* p) {
    uint32_t a;
    asm("{ .reg .u64 t; cvta.to.shared.u64 t, %1; cvt.u32.u64 %0, t; }"
        : "=r"(a) : "l"(p));
    return a;
}

#define CP16(dst, src) \
    asm volatile("cp.async.cg.shared.global [%0], [%1], 16;" \
                 :: "r"(dst), "l"(src))
#define CP_COMMIT() asm volatile("cp.async.commit_group;")
#define CP_WAIT1() asm volatile("cp.async.wait_group 1;")
#define CP_WAIT0() asm volatile("cp.async.wait_group 0;")

#define LDSM_X4(r, a)                                                       \
    asm volatile("ldmatrix.sync.aligned.m8n8.x4.shared.b16 "                \
                 "{%0,%1,%2,%3}, [%4];"                                     \
                 : "=r"((r)[0]), "=r"((r)[1]), "=r"((r)[2]), "=r"((r)[3])   \
                 : "r"(a))

#define MMA_BF16(d, a, b0, b1)                                              \
    asm volatile("mma.sync.aligned.m16n8k16.row.col.f32.bf16.bf16.f32 "     \
                 "{%0,%1,%2,%3},{%4,%5,%6,%7},{%8,%9},{%0,%1,%2,%3};"       \
                 : "+f"((d)[0]), "+f"((d)[1]), "+f"((d)[2]), "+f"((d)[3])   \
                 : "r"((a)[0]), "r"((a)[1]), "r"((a)[2]), "r"((a)[3]),      \
                   "r"(b0), "r"(b1))

// FFMA-only exp2 for t <= 0 (deg-6 poly, rel err ~1.2e-7)
__device__ __forceinline__ float exp2p(float t) {
    t = fmaxf(t, -80.0f);
    float y = __fadd_rn(t, 12582912.0f);
    int n = __float_as_int(y) - 0x4B400000;
    float f = __fsub_rn(t, __fsub_rn(y, 12582912.0f));
    float p = 1.54035304e-4f;
    p = fmaf(p, f, 1.33335581e-3f);
    p = fmaf(p, f, 9.61812911e-3f);
    p = fmaf(p, f, 5.55041087e-2f);
    p = fmaf(p, f, 2.40226507e-1f);
    p = fmaf(p, f, 6.93147181e-1f);
    p = fmaf(p, f, 1.0f);
    return __int_as_float(__float_as_int(p) + (n << 23));
}

__device__ __forceinline__ uint32_t pack_bf2(float lo, float hi) {
    __nv_bfloat162 h = __floats2bfloat162_rn(lo, hi);
    return *(uint32_t*)&h;
}

// Write an fp32 pair as (hi, lo) bf16x2 pairs
__device__ __forceinline__ void store_split2(__nv_bfloat16* Hp,
                                             __nv_bfloat16* Lp, size_t off,
                                             float v0, float v1) {
    __nv_bfloat162 hh = __floats2bfloat162_rn(v0, v1);
    *(__nv_bfloat162*)(Hp + off) = hh;
    __nv_bfloat162 ll = __floats2bfloat162_rn(v0 - __bfloat162float(hh.x),
                                              v1 - __bfloat162float(hh.y));
    *(__nv_bfloat162*)(Lp + off) = ll;
}

// ---------------------------------------------------------------------------
// fp32 -> (hi, lo) bf16 split (x input)
// ---------------------------------------------------------------------------
__global__ void split_kernel(const float* __restrict__ in,
                             __nv_bfloat16* __restrict__ hi,
                             __nv_bfloat16* __restrict__ lo, int n) {
    int i = blockIdx.x * blockDim.x + threadIdx.x;
    if (i >= n) return;
    float v = in[i];
    __nv_bfloat16 h = __float2bfloat16(v);
    hi[i] = h;
    lo[i] = __float2bfloat16(v - __bfloat162float(h));
}

// All 4 weights in one launch (g_wh/g_wl are [4][NW] contiguous)
__global__ void split4_kernel(const float* __restrict__ w0,
                              const float* __restrict__ w1,
                              const float* __restrict__ w2,
                              const float* __restrict__ w3,
                              __nv_bfloat16* __restrict__ hi,
                              __nv_bfloat16* __restrict__ lo) {
    int i = blockIdx.x * blockDim.x + threadIdx.x;
    int sel = i >> 20;  // NW = 1<<20
    int off = i & ((1 << 20) - 1);
    const float* src = (sel == 0) ? w0 : (sel == 1) ? w1 : (sel == 2) ? w2 : w3;
    float v = src[off];
    __nv_bfloat16 h = __float2bfloat16(v);
    hi[i] = h;
    lo[i] = __float2bfloat16(v - __bfloat162float(h));
}

// ---------------------------------------------------------------------------
// sin/cos table (exact range reduction)
// ---------------------------------------------------------------------------
__global__ void sincos_table_kernel(const int* __restrict__ pos) {
    int idx = blockIdx.x * blockDim.x + threadIdx.x;
    if (idx >= S_ * 32) return;
    int s = idx >> 5;
    int p = idx & 31;
    float invf = (float)exp2(-(double)p * 0.4152410118609203);
    float ang = (float)pos[s] * invf;
    double a = (double)ang;
    double kq = floor(a * 0.15915494309189535);
    float r = (float)(a - kq * 6.283185307179586);
    float sn, cs;
    sincosf(r, &sn, &cs);
    g_sc[idx] = make_float2(sn, cs);
}

// ---------------------------------------------------------------------------
// Fused QKV GEMM: grid.z selects {Q, K, V}. Shared structure with R4 GEMM.
// z=0: epilogue rope(+qscale) -> qh/ql bf16 [B,H,S,64]
// z=1: epilogue rope          -> kh/kl bf16 [B,H,S,64]
// z=2: plain f32 headed write -> g_v (vsplit_t transposes after)
// ---------------------------------------------------------------------------
#define NCHUNK 32
#define STRIDE 80
#define TILE_B (128 * STRIDE)
#define STAGE_B (4 * TILE_B)
#define GSMEM (2 * STAGE_B)

__device__ __forceinline__ void gemm_core(
    const __nv_bfloat16* __restrict__ Ah, const __nv_bfloat16* __restrict__ Al,
    const __nv_bfloat16* __restrict__ Bh, const __nv_bfloat16* __restrict__ Bl,
    char* sm, float acc[2][8][4], int m0, int n0) {
    uint32_t sb = smem_u32(sm);
    int tid = threadIdx.x;
    int lane = tid & 31;
    int wid = tid >> 5;
    int warp_m = wid & 3;
    int warp_n = wid >> 2;

    const __nv_bfloat16* gsrc[4] = {
        Ah + (size_t)m0 * D_, Al + (size_t)m0 * D_,
        Bh + (size_t)n0 * D_, Bl + (size_t)n0 * D_};

    int ldrow = tid >> 2;
    int ldc16 = tid & 3;

    auto load_stage = [&](int c) {
        uint32_t dbase = sb + (c & 1) * STAGE_B;
#pragma unroll
        for (int op = 0; op < 4; op++) {
#pragma unroll
            for (int i = 0; i < 2; i++) {
                int row = ldrow + i * 64;
                uint32_t dst = dbase + op * TILE_B + row * STRIDE + ldc16 * 16;
                const __nv_bfloat16* src =
                    gsrc[op] + (size_t)row * D_ + c * 32 + ldc16 * 8;
                CP16(dst, src);
            }
        }
        CP_COMMIT();
    };

    load_stage(0);
    load_stage(1);

#pragma unroll
    for (int mt = 0; mt < 2; mt++)
#pragma unroll
        for (int nt = 0; nt < 8; nt++)
#pragma unroll
            for (int r = 0; r < 4; r++) acc[mt][nt][r] = 0.0f;

    for (int c = 0; c < NCHUNK; c++) {
        if (c < NCHUNK - 1) CP_WAIT1(); else CP_WAIT0();
        __syncthreads();
        uint32_t base = sb + (c & 1) * STAGE_B;

#pragma unroll
        for (int s = 0; s < 2; s++) {
            int co = s * 32;
            uint32_t ah[2][4], al[2][4];
#pragma unroll
            for (int mt = 0; mt < 2; mt++) {
                uint32_t addr = base +
                    (warp_m * 32 + mt * 16 + (lane & 15)) * STRIDE +
                    ((lane >> 4) << 4) + co;
                LDSM_X4(ah[mt], addr);
                LDSM_X4(al[mt], addr + TILE_B);
            }
            uint32_t bh[4][4], bl[4][4];
#pragma unroll
            for (int p = 0; p < 4; p++) {
                uint32_t addr = base + 2 * TILE_B +
                    (warp_n * 64 + p * 16 + ((lane >> 4) << 3) + (lane & 7)) * STRIDE +
                    (((lane >> 3) & 1) << 4) + co;
                LDSM_X4(bh[p], addr);
                LDSM_X4(bl[p], addr + TILE_B);
            }
#pragma unroll
            for (int mt = 0; mt < 2; mt++)
#pragma unroll
                for (int nt = 0; nt < 8; nt++) {
                    int p = nt >> 1, hf = (nt & 1) * 2;
                    MMA_BF16(acc[mt][nt], ah[mt], bh[p][hf], bh[p][hf + 1]);
                    MMA_BF16(acc[mt][nt], ah[mt], bl[p][hf], bl[p][hf + 1]);
                    MMA_BF16(acc[mt][nt], al[mt], bh[p][hf], bh[p][hf + 1]);
                }
        }
        __syncthreads();
        if (c + 2 < NCHUNK) load_stage(c + 2);
    }
}

__global__ void __launch_bounds__(256, 1) gemm_qkv(
    const __nv_bfloat16* __restrict__ Xh, const __nv_bfloat16* __restrict__ Xl) {
    extern __shared__ char sm[];
    int z = blockIdx.z;
    int m0 = blockIdx.y * 128;
    int n0 = blockIdx.x * 128;

    const __nv_bfloat16* Bh = g_wh[z];
    const __nv_bfloat16* Bl = g_wl[z];

    float acc[2][8][4];
    gemm_core(Xh, Xl, Bh, Bl, sm, acc, m0, n0);

    int lane = threadIdx.x & 31;
    int wid = threadIdx.x >> 5;
    int warp_m = wid & 3;
    int warp_n = wid >> 2;
    const float QSCALE = 0.125f * 1.4426950408889634f;

#pragma unroll
    for (int mt = 0; mt < 2; mt++)
#pragma unroll
        for (int nt = 0; nt < 8; nt++)
#pragma unroll
            for (int half = 0; half < 2; half++) {
                int m = m0 + warp_m * 32 + mt * 16 + (lane >> 2) + half * 8;
                int n = n0 + warp_n * 64 + nt * 8 + (lane & 3) * 2;
                float v0 = acc[mt][nt][half * 2];
                float v1 = acc[mt][nt][half * 2 + 1];
                int b = m >> 11, s = m & (S_ - 1), h = n >> 6, d = n & 63;
                size_t off = ((((size_t)b * H_ + h) * S_ + s) << 6) + d;
                if (z == 2) {
                    *(float2*)&g_v[off] = make_float2(v0, v1);
                } else {
                    float2 sc = g_sc[(s << 5) | (d >> 1)];  // d even
                    float y0 = v0 * sc.y - v1 * sc.x;
                    float y1 = v0 * sc.x + v1 * sc.y;
                    if (z == 0) {
                        y0 *= QSCALE; y1 *= QSCALE;
                        store_split2(g_qh, g_ql, off, y0, y1);
                    } else {
                        store_split2(g_kh, g_kl, off, y0, y1);
                    }
                }
            }
}

// Wo GEMM: attn(bf16 split) @ Wo^T -> f32 out (plain layout)
__global__ void __launch_bounds__(256, 1) gemm_out(float* __restrict__ C) {
    extern __shared__ char sm[];
    int m0 = blockIdx.y * 128;
    int n0 = blockIdx.x * 128;
    float acc[2][8][4];
    gemm_core(g_ah, g_al, g_wh[3], g_wl[3], sm, acc, m0, n0);

    int lane = threadIdx.x & 31;
    int wid = threadIdx.x >> 5;
    int warp_m = wid & 3;
    int warp_n = wid >> 2;
#pragma unroll
    for (int mt = 0; mt < 2; mt++)
#pragma unroll
        for (int nt = 0; nt < 8; nt++)
#pragma unroll
            for (int half = 0; half < 2; half++) {
                int m = m0 + warp_m * 32 + mt * 16 + (lane >> 2) + half * 8;
                int n = n0 + warp_n * 64 + nt * 8 + (lane & 3) * 2;
                *(float2*)&C[(size_t)m * D_ + n] =
                    make_float2(acc[mt][nt][half * 2], acc[mt][nt][half * 2 + 1]);
            }
}

// ---------------------------------------------------------------------------
// V: split + transpose to [B,H,64,S]
// ---------------------------------------------------------------------------
__global__ void __launch_bounds__(256) vsplit_t_kernel(
    const float* __restrict__ V, __nv_bfloat16* __restrict__ Vth,
    __nv_bfloat16* __restrict__ Vtl) {
    __shared__ float t[64][65];
    int bh = blockIdx.y;
    int s0 = blockIdx.x * 64;
    int tid = threadIdx.x;
#pragma unroll
    for (int i = 0; i < 16; i++) {
        int e = tid + i * 256;
        int s = e >> 6, d = e & 63;
        t[d][s] = V[((size_t)bh * S_ + s0 + s) * 64 + d];
    }
    __syncthreads();
#pragma unroll
    for (int i = 0; i < 16; i++) {
        int e = tid + i * 256;
        int d = e >> 6, sj = e & 63;
        float val = t[d][sj];
        __nv_bfloat16 h = __float2bfloat16(val);
        size_t o = ((size_t)bh * 64 + d) * S_ + s0 + sj;
        Vth[o] = h;
        Vtl[o] = __float2bfloat16(val - __bfloat162float(h));
    }
}

// ---------------------------------------------------------------------------
// Tensor-core causal flash attention (bf16 split, fp32 accum, poly exp2).
// Heavy q-tiles scheduled first (qtile reversed). Epilogue writes bf16 split.
// ---------------------------------------------------------------------------
#define AST 144
#define AQ_B (128 * AST)
#define AKV_TILE (64 * AST)
#define AKV_STAGE (4 * AKV_TILE)
#define A_OST (2 * AQ_B)
#define ASMEM (A_OST + 2 * AKV_STAGE)

__global__ void __launch_bounds__(128, 2) attn_mma(
    const __nv_bfloat16* __restrict__ Qh, const __nv_bfloat16* __restrict__ Ql,
    const __nv_bfloat16* __restrict__ Kh, const __nv_bfloat16* __restrict__ Kl,
    const __nv_bfloat16* __restrict__ Vth, const __nv_bfloat16* __restrict__ Vtl,
    __nv_bfloat16* __restrict__ Oh, __nv_bfloat16* __restrict__ Ol) {
    extern __shared__ char sm[];
    uint32_t sb = smem_u32(sm);
    int tid = threadIdx.x;
    int lane = tid & 31;
    int wm = tid >> 5;
    int bh = blockIdx.y;
    int qtile = gridDim.x - 1 - blockIdx.x;  // heavy tiles first
    int q0 = qtile * 128;
    size_t bhS = (size_t)bh * S_;
    int g = lane >> 2, t4 = lane & 3;

    {
        const __nv_bfloat16* sh = Qh + (bhS + q0 + tid) * 64;
        const __nv_bfloat16* sl = Ql + (bhS + q0 + tid) * 64;
        uint32_t dh = sb + tid * AST;
        uint32_t dl = sb + AQ_B + tid * AST;
#pragma unroll
        for (int c = 0; c < 8; c++) {
            CP16(dh + c * 16, sh + c * 8);
            CP16(dl + c * 16, sl + c * 8);
        }
        CP_COMMIT();
    }

    int nblocks = qtile * 2 + 2;

    int krow = tid >> 1;
    int hc = (tid & 1) * 4;
    auto load_kv = [&](int c) {
        uint32_t base = sb + A_OST + (c & 1) * AKV_STAGE;
        int kb = c * 64;
        const __nv_bfloat16* skh = Kh + (bhS + kb + krow) * 64 + hc * 8;
        const __nv_bfloat16* skl = Kl + (bhS + kb + krow) * 64 + hc * 8;
        const __nv_bfloat16* svh = Vth + ((size_t)bh * 64 + krow) * S_ + kb + hc * 8;
        const __nv_bfloat16* svl = Vtl + ((size_t)bh * 64 + krow) * S_ + kb + hc * 8;
        uint32_t d0 = base + krow * AST + hc * 16;
#pragma unroll
        for (int i = 0; i < 4; i++) {
            CP16(d0 + i * 16, skh + i * 8);
            CP16(d0 + AKV_TILE + i * 16, skl + i * 8);
            CP16(d0 + 2 * AKV_TILE + i * 16, svh + i * 8);
            CP16(d0 + 3 * AKV_TILE + i * 16, svl + i * 8);
        }
        CP_COMMIT();
    };
    load_kv(0);
    load_kv(1);

    float o[2][8][4];
    float Sv[2][8][4];
    float mr[2][2], lr[2][2];
#pragma unroll
    for (int mt = 0; mt < 2; mt++) {
#pragma unroll
        for (int nt = 0; nt < 8; nt++)
#pragma unroll
            for (int r = 0; r < 4; r++) o[mt][nt][r] = 0.0f;
        mr[mt][0] = mr[mt][1] = -INFINITY;
        lr[mt][0] = lr[mt][1] = 0.0f;
    }

    for (int c = 0; c < nblocks; c++) {
        if (c == nblocks - 1) CP_WAIT0(); else CP_WAIT1();
        __syncthreads();
        uint32_t base = sb + A_OST + (c & 1) * AKV_STAGE;
        int kb = c * 64;

#pragma unroll
        for (int mt = 0; mt < 2; mt++)
#pragma unroll
            for (int nt = 0; nt < 8; nt++)
#pragma unroll
                for (int r = 0; r < 4; r++) Sv[mt][nt][r] = 0.0f;

#pragma unroll
        for (int ks = 0; ks < 4; ks++) {
            uint32_t ah[2][4], al[2][4];
#pragma unroll
            for (int mt = 0; mt < 2; mt++) {
                uint32_t qa = sb + (wm * 32 + mt * 16 + (lane & 15)) * AST +
                              ks * 32 + ((lane >> 4) << 4);
                LDSM_X4(ah[mt], qa);
                LDSM_X4(al[mt], qa + AQ_B);
            }
#pragma unroll
            for (int ntp = 0; ntp < 4; ntp++) {
                uint32_t ba = base +
                    (ntp * 16 + ((lane >> 4) << 3) + (lane & 7)) * AST +
                    ks * 32 + (((lane >> 3) & 1) << 4);
                uint32_t bhf[4], blf[4];
                LDSM_X4(bhf, ba);
                LDSM_X4(blf, ba + AKV_TILE);
#pragma unroll
                for (int mt = 0; mt < 2; mt++)
#pragma unroll
                    for (int sub = 0; sub < 2; sub++) {
                        int nt = ntp * 2 + sub;
                        MMA_BF16(Sv[mt][nt], ah[mt], bhf[sub * 2], bhf[sub * 2 + 1]);
                        MMA_BF16(Sv[mt][nt], ah[mt], blf[sub * 2], blf[sub * 2 + 1]);
                        MMA_BF16(Sv[mt][nt], al[mt], bhf[sub * 2], bhf[sub * 2 + 1]);
                    }
            }
        }

        if (kb + 63 > q0 + wm * 32) {
#pragma unroll
            for (int mt = 0; mt < 2; mt++)
#pragma unroll
                for (int nt = 0; nt < 8; nt++)
#pragma unroll
                    for (int r = 0; r < 4; r++) {
                        int col = kb + nt * 8 + t4 * 2 + (r & 1);
                        int row = q0 + wm * 32 + mt * 16 + g + (r >> 1) * 8;
                        if (col > row) Sv[mt][nt][r] = -INFINITY;
                    }
        }

#pragma unroll
        for (int mt = 0; mt < 2; mt++)
#pragma unroll
            for (int h = 0; h < 2; h++) {
                float mx = Sv[mt][0][2 * h];
#pragma unroll
                for (int nt = 0; nt < 8; nt++) {
                    mx = fmaxf(mx, Sv[mt][nt][2 * h]);
                    mx = fmaxf(mx, Sv[mt][nt][2 * h + 1]);
                }
                mx = fmaxf(mx, __shfl_xor_sync(0xffffffff, mx, 1));
                mx = fmaxf(mx, __shfl_xor_sync(0xffffffff, mx, 2));
                float mn = fmaxf(mr[mt][h], mx);
                float alpha = exp2p(mr[mt][h] - mn);
                mr[mt][h] = mn;
                float ps = 0.0f;
#pragma unroll
                for (int nt = 0; nt < 8; nt++) {
                    o[mt][nt][2 * h] *= alpha;
                    o[mt][nt][2 * h + 1] *= alpha;
                    float p0 = exp2p(Sv[mt][nt][2 * h] - mn);
                    float p1 = exp2p(Sv[mt][nt][2 * h + 1] - mn);
                    Sv[mt][nt][2 * h] = p0;
                    Sv[mt][nt][2 * h + 1] = p1;
                    ps += p0 + p1;
                }
                ps += __shfl_xor_sync(0xffffffff, ps, 1);
                ps += __shfl_xor_sync(0xffffffff, ps, 2);
                lr[mt][h] = lr[mt][h] * alpha + ps;
            }

#pragma unroll
        for (int ks = 0; ks < 4; ks++) {
            uint32_t ph[2][4], pl[2][4];
#pragma unroll
            for (int mt = 0; mt < 2; mt++)
#pragma unroll
                for (int u = 0; u < 4; u++) {
                    int nt = 2 * ks + (u >> 1);
                    int r0 = (u & 1) * 2;
                    float p0 = Sv[mt][nt][r0], p1 = Sv[mt][nt][r0 + 1];
                    __nv_bfloat162 hh = __floats2bfloat162_rn(p0, p1);
                    ph[mt][u] = *(uint32_t*)&hh;
                    pl[mt][u] = pack_bf2(p0 - __bfloat162float(hh.x),
                                         p1 - __bfloat162float(hh.y));
                }
#pragma unroll
            for (int ntp = 0; ntp < 4; ntp++) {
                uint32_t va = base + 2 * AKV_TILE +
                    (ntp * 16 + ((lane >> 4) << 3) + (lane & 7)) * AST +
                    ks * 32 + (((lane >> 3) & 1) << 4);
                uint32_t bvh[4], bvl[4];
                LDSM_X4(bvh, va);
                LDSM_X4(bvl, va + AKV_TILE);
#pragma unroll
                for (int mt = 0; mt < 2; mt++)
#pragma unroll
                    for (int sub = 0; sub < 2; sub++) {
                        int nt = ntp * 2 + sub;
                        MMA_BF16(o[mt][nt], ph[mt], bvh[sub * 2], bvh[sub * 2 + 1]);
                        MMA_BF16(o[mt][nt], ph[mt], bvl[sub * 2], bvl[sub * 2 + 1]);
                        MMA_BF16(o[mt][nt], pl[mt], bvh[sub * 2], bvh[sub * 2 + 1]);
                    }
            }
        }

        __syncthreads();
        if (c + 2 < nblocks) load_kv(c + 2);
    }

    // Epilogue: normalize + bf16 hi/lo split write to [B,S,H,64]
    int b = bh >> 4, hh = bh & 15;
#pragma unroll
    for (int mt = 0; mt < 2; mt++)
#pragma unroll
        for (int h = 0; h < 2; h++) {
            float inv = 1.0f / lr[mt][h];
            int row = q0 + wm * 32 + mt * 16 + g + 8 * h;
#pragma unroll
            for (int nt = 0; nt < 8; nt++) {
                int d = nt * 8 + t4 * 2;
                size_t off = (((size_t)b * S_ + row) * H_ + hh) * 64 + d;
                store_split2(Oh, Ol, off, o[mt][nt][2 * h] * inv,
                             o[mt][nt][2 * h + 1] * inv);
            }
        }
}

// ---------------------------------------------------------------------------
// Launch
// ---------------------------------------------------------------------------
extern "C" void kernel_launch(void* const* d_in, const int* in_sizes, int n_in,
                              void* d_out, int out_size) {
    const float* x = (const float*)d_in[0];
    const float* Wq = (const float*)d_in[1];
    const float* Wk = (const float*)d_in[2];
    const float* Wv = (const float*)d_in[3];
    const float* Wo = (const float*)d_in[4];
    const int* pos = (const int*)d_in[5];

    float* v;
    __nv_bfloat16 *xh, *xl, *ah, *al, *wh, *wl;
    __nv_bfloat16 *qh, *ql, *kh, *kl, *vth, *vtl;
    cudaGetSymbolAddress((void**)&v, g_v);
    cudaGetSymbolAddress((void**)&xh, g_xh);
    cudaGetSymbolAddress((void**)&xl, g_xl);
    cudaGetSymbolAddress((void**)&ah, g_ah);
    cudaGetSymbolAddress((void**)&al, g_al);
    cudaGetSymbolAddress((void**)&wh, g_wh);
    cudaGetSymbolAddress((void**)&wl, g_wl);
    cudaGetSymbolAddress((void**)&qh, g_qh);
    cudaGetSymbolAddress((void**)&ql, g_ql);
    cudaGetSymbolAddress((void**)&kh, g_kh);
    cudaGetSymbolAddress((void**)&kl, g_kl);
    cudaGetSymbolAddress((void**)&vth, g_vth);
    cudaGetSymbolAddress((void**)&vtl, g_vtl);

    cudaFuncSetAttribute(gemm_qkv,
                         cudaFuncAttributeMaxDynamicSharedMemorySize, GSMEM);
    cudaFuncSetAttribute(gemm_out,
                         cudaFuncAttributeMaxDynamicSharedMemorySize, GSMEM);
    cudaFuncSetAttribute(attn_mma,
                         cudaFuncAttributeMaxDynamicSharedMemorySize, ASMEM);

    sincos_table_kernel<<<(S_ * 32) / 256, 256>>>(pos);

    const int NX = B_ * S_ * D_;  // 4M
    split_kernel<<<NX / 256, 256>>>(x, xh, xl, NX);
    split4_kernel<<<(4 * D_ * D_) / 256, 256>>>(Wq, Wk, Wv, Wo, wh, wl);

    gemm_qkv<<<dim3(D_ / 128, (B_ * S_) / 128, 3), 256, GSMEM>>>(xh, xl);

    vsplit_t_kernel<<<dim3(S_ / 64, B_ * H_), 256>>>(v, vth, vtl);

    attn_mma<<<dim3(S_ / 128, B_ * H_), 128, ASMEM>>>(qh, ql, kh, kl, vth, vtl,
                                                      ah, al);

    gemm_out<<<dim3(D_ / 128, (B_ * S_) / 128), 256, GSMEM>>>((float*)d_out);
}

// round 12
// speedup vs baseline: 1.6701x; 1.6701x over previous
#include <cuda_runtime.h>
#include <cuda_bf16.h>
#include <math.h>
#include <cstdint>

// Problem constants
#define B_ 2
#define S_ 2048
#define D_ 1024
#define H_ 16
#define DK_ 64

// ---------------------------------------------------------------------------
// Scratch (__device__ globals; no allocation allowed)
// ---------------------------------------------------------------------------
__device__ float g_v[B_ * S_ * D_];  // [B,H,S,64] f32 (pre-transpose V)
__device__ float2 g_sc[S_ * 32];

// bf16 split buffers
__device__ __nv_bfloat16 g_xh[B_ * S_ * D_];
__device__ __nv_bfloat16 g_xl[B_ * S_ * D_];
__device__ __nv_bfloat16 g_ah[B_ * S_ * D_];   // attn out hi [B,S,H,64]
__device__ __nv_bfloat16 g_al[B_ * S_ * D_];
__device__ __nv_bfloat16 g_wh[4][D_ * D_];
__device__ __nv_bfloat16 g_wl[4][D_ * D_];

__device__ __nv_bfloat16 g_qh[B_ * S_ * D_];   // [B,H,S,64], rope+scaled
__device__ __nv_bfloat16 g_ql[B_ * S_ * D_];
__device__ __nv_bfloat16 g_kh[B_ * S_ * D_];   // [B,H,S,64], rope
__device__ __nv_bfloat16 g_kl[B_ * S_ * D_];
__device__ __nv_bfloat16 g_vth[B_ * S_ * D_];  // [B,H,64,S]
__device__ __nv_bfloat16 g_vtl[B_ * S_ * D_];

// ---------------------------------------------------------------------------
// PTX helpers (baseline ISA: mma.sync / ldmatrix / cp.async — sm_103-safe)
// ---------------------------------------------------------------------------
__device__ __forceinline__ uint32_t smem_u32(const void* p) {
    uint32_t a;
    asm("{ .reg .u64 t; cvta.to.shared.u64 t, %1; cvt.u32.u64 %0, t; }"
        : "=r"(a) : "l"(p));
    return a;
}

#define CP16(dst, src) \
    asm volatile("cp.async.cg.shared.global [%0], [%1], 16;" \
                 :: "r"(dst), "l"(src))
#define CP_COMMIT() asm volatile("cp.async.commit_group;")
#define CP_WAIT1() asm volatile("cp.async.wait_group 1;")
#define CP_WAIT0() asm volatile("cp.async.wait_group 0;")

#define LDSM_X4(r, a)                                                       \
    asm volatile("ldmatrix.sync.aligned.m8n8.x4.shared.b16 "                \
                 "{%0,%1,%2,%3}, [%4];"                                     \
                 : "=r"((r)[0]), "=r"((r)[1]), "=r"((r)[2]), "=r"((r)[3])   \
                 : "r"(a))

#define MMA_BF16(d, a, b0, b1)                                              \
    asm volatile("mma.sync.aligned.m16n8k16.row.col.f32.bf16.bf16.f32 "     \
                 "{%0,%1,%2,%3},{%4,%5,%6,%7},{%8,%9},{%0,%1,%2,%3};"       \
                 : "+f"((d)[0]), "+f"((d)[1]), "+f"((d)[2]), "+f"((d)[3])   \
                 : "r"((a)[0]), "r"((a)[1]), "r"((a)[2]), "r"((a)[3]),      \
                   "r"(b0), "r"(b1))

// FFMA-only exp2 for t <= 0 (deg-6 poly, rel err ~1.2e-7)
__device__ __forceinline__ float exp2p(float t) {
    t = fmaxf(t, -80.0f);
    float y = __fadd_rn(t, 12582912.0f);
    int n = __float_as_int(y) - 0x4B400000;
    float f = __fsub_rn(t, __fsub_rn(y, 12582912.0f));
    float p = 1.54035304e-4f;
    p = fmaf(p, f, 1.33335581e-3f);
    p = fmaf(p, f, 9.61812911e-3f);
    p = fmaf(p, f, 5.55041087e-2f);
    p = fmaf(p, f, 2.40226507e-1f);
    p = fmaf(p, f, 6.93147181e-1f);
    p = fmaf(p, f, 1.0f);
    return __int_as_float(__float_as_int(p) + (n << 23));
}

__device__ __forceinline__ uint32_t pack_bf2(float lo, float hi) {
    __nv_bfloat162 h = __floats2bfloat162_rn(lo, hi);
    return *(uint32_t*)&h;
}

// Write an fp32 pair as (hi, lo) bf16x2 pairs
__device__ __forceinline__ void store_split2(__nv_bfloat16* Hp,
                                             __nv_bfloat16* Lp, size_t off,
                                             float v0, float v1) {
    __nv_bfloat162 hh = __floats2bfloat162_rn(v0, v1);
    *(__nv_bfloat162*)(Hp + off) = hh;
    __nv_bfloat162 ll = __floats2bfloat162_rn(v0 - __bfloat162float(hh.x),
                                              v1 - __bfloat162float(hh.y));
    *(__nv_bfloat162*)(Lp + off) = ll;
}

// ---------------------------------------------------------------------------
// fp32 -> (hi, lo) bf16 split (x input)
// ---------------------------------------------------------------------------
__global__ void split_kernel(const float* __restrict__ in,
                             __nv_bfloat16* __restrict__ hi,
                             __nv_bfloat16* __restrict__ lo, int n) {
    int i = blockIdx.x * blockDim.x + threadIdx.x;
    if (i >= n) return;
    float v = in[i];
    __nv_bfloat16 h = __float2bfloat16(v);
    hi[i] = h;
    lo[i] = __float2bfloat16(v - __bfloat162float(h));
}

// All 4 weights in one launch (g_wh/g_wl are [4][NW] contiguous)
__global__ void split4_kernel(const float* __restrict__ w0,
                              const float* __restrict__ w1,
                              const float* __restrict__ w2,
                              const float* __restrict__ w3,
                              __nv_bfloat16* __restrict__ hi,
                              __nv_bfloat16* __restrict__ lo) {
    int i = blockIdx.x * blockDim.x + threadIdx.x;
    int sel = i >> 20;  // NW = 1<<20
    int off = i & ((1 << 20) - 1);
    const float* src = (sel == 0) ? w0 : (sel == 1) ? w1 : (sel == 2) ? w2 : w3;
    float v = src[off];
    __nv_bfloat16 h = __float2bfloat16(v);
    hi[i] = h;
    lo[i] = __float2bfloat16(v - __bfloat162float(h));
}

// ---------------------------------------------------------------------------
// sin/cos table (exact range reduction)
// ---------------------------------------------------------------------------
__global__ void sincos_table_kernel(const int* __restrict__ pos) {
    int idx = blockIdx.x * blockDim.x + threadIdx.x;
    if (idx >= S_ * 32) return;
    int s = idx >> 5;
    int p = idx & 31;
    float invf = (float)exp2(-(double)p * 0.4152410118609203);
    float ang = (float)pos[s] * invf;
    double a = (double)ang;
    double kq = floor(a * 0.15915494309189535);
    float r = (float)(a - kq * 6.283185307179586);
    float sn, cs;
    sincosf(r, &sn, &cs);
    g_sc[idx] = make_float2(sn, cs);
}

// ---------------------------------------------------------------------------
// Fused QKV GEMM (launch_bounds(256,2) caps regs at 128 -> 2 CTAs/SM).
// z=0: rope(+qscale) -> qh/ql; z=1: rope -> kh/kl; z=2: f32 headed -> g_v
// ---------------------------------------------------------------------------
#define NCHUNK 32
#define STRIDE 80
#define TILE_B (128 * STRIDE)
#define STAGE_B (4 * TILE_B)
#define GSMEM (2 * STAGE_B)

__device__ __forceinline__ void gemm_core(
    const __nv_bfloat16* __restrict__ Ah, const __nv_bfloat16* __restrict__ Al,
    const __nv_bfloat16* __restrict__ Bh, const __nv_bfloat16* __restrict__ Bl,
    char* sm, float acc[2][8][4], int m0, int n0) {
    uint32_t sb = smem_u32(sm);
    int tid = threadIdx.x;
    int lane = tid & 31;
    int wid = tid >> 5;
    int warp_m = wid & 3;
    int warp_n = wid >> 2;

    const __nv_bfloat16* gsrc[4] = {
        Ah + (size_t)m0 * D_, Al + (size_t)m0 * D_,
        Bh + (size_t)n0 * D_, Bl + (size_t)n0 * D_};

    int ldrow = tid >> 2;
    int ldc16 = tid & 3;

    auto load_stage = [&](int c) {
        uint32_t dbase = sb + (c & 1) * STAGE_B;
#pragma unroll
        for (int op = 0; op < 4; op++) {
#pragma unroll
            for (int i = 0; i < 2; i++) {
                int row = ldrow + i * 64;
                uint32_t dst = dbase + op * TILE_B + row * STRIDE + ldc16 * 16;
                const __nv_bfloat16* src =
                    gsrc[op] + (size_t)row * D_ + c * 32 + ldc16 * 8;
                CP16(dst, src);
            }
        }
        CP_COMMIT();
    };

    load_stage(0);
    load_stage(1);

#pragma unroll
    for (int mt = 0; mt < 2; mt++)
#pragma unroll
        for (int nt = 0; nt < 8; nt++)
#pragma unroll
            for (int r = 0; r < 4; r++) acc[mt][nt][r] = 0.0f;

    for (int c = 0; c < NCHUNK; c++) {
        if (c < NCHUNK - 1) CP_WAIT1(); else CP_WAIT0();
        __syncthreads();
        uint32_t base = sb + (c & 1) * STAGE_B;

#pragma unroll
        for (int s = 0; s < 2; s++) {
            int co = s * 32;
            uint32_t ah[2][4], al[2][4];
#pragma unroll
            for (int mt = 0; mt < 2; mt++) {
                uint32_t addr = base +
                    (warp_m * 32 + mt * 16 + (lane & 15)) * STRIDE +
                    ((lane >> 4) << 4) + co;
                LDSM_X4(ah[mt], addr);
                LDSM_X4(al[mt], addr + TILE_B);
            }
            uint32_t bh[4][4], bl[4][4];
#pragma unroll
            for (int p = 0; p < 4; p++) {
                uint32_t addr = base + 2 * TILE_B +
                    (warp_n * 64 + p * 16 + ((lane >> 4) << 3) + (lane & 7)) * STRIDE +
                    (((lane >> 3) & 1) << 4) + co;
                LDSM_X4(bh[p], addr);
                LDSM_X4(bl[p], addr + TILE_B);
            }
#pragma unroll
            for (int mt = 0; mt < 2; mt++)
#pragma unroll
                for (int nt = 0; nt < 8; nt++) {
                    int p = nt >> 1, hf = (nt & 1) * 2;
                    MMA_BF16(acc[mt][nt], ah[mt], bh[p][hf], bh[p][hf + 1]);
                    MMA_BF16(acc[mt][nt], ah[mt], bl[p][hf], bl[p][hf + 1]);
                    MMA_BF16(acc[mt][nt], al[mt], bh[p][hf], bh[p][hf + 1]);
                }
        }
        __syncthreads();
        if (c + 2 < NCHUNK) load_stage(c + 2);
    }
}

__global__ void __launch_bounds__(256, 2) gemm_qkv(
    const __nv_bfloat16* __restrict__ Xh, const __nv_bfloat16* __restrict__ Xl) {
    extern __shared__ char sm[];
    int z = blockIdx.z;
    int m0 = blockIdx.y * 128;
    int n0 = blockIdx.x * 128;

    const __nv_bfloat16* Bh = g_wh[z];
    const __nv_bfloat16* Bl = g_wl[z];

    float acc[2][8][4];
    gemm_core(Xh, Xl, Bh, Bl, sm, acc, m0, n0);

    int lane = threadIdx.x & 31;
    int wid = threadIdx.x >> 5;
    int warp_m = wid & 3;
    int warp_n = wid >> 2;
    const float QSCALE = 0.125f * 1.4426950408889634f;

#pragma unroll
    for (int mt = 0; mt < 2; mt++)
#pragma unroll
        for (int nt = 0; nt < 8; nt++)
#pragma unroll
            for (int half = 0; half < 2; half++) {
                int m = m0 + warp_m * 32 + mt * 16 + (lane >> 2) + half * 8;
                int n = n0 + warp_n * 64 + nt * 8 + (lane & 3) * 2;
                float v0 = acc[mt][nt][half * 2];
                float v1 = acc[mt][nt][half * 2 + 1];
                int b = m >> 11, s = m & (S_ - 1), h = n >> 6, d = n & 63;
                size_t off = ((((size_t)b * H_ + h) * S_ + s) << 6) + d;
                if (z == 2) {
                    *(float2*)&g_v[off] = make_float2(v0, v1);
                } else {
                    float2 sc = g_sc[(s << 5) | (d >> 1)];  // d even
                    float y0 = v0 * sc.y - v1 * sc.x;
                    float y1 = v0 * sc.x + v1 * sc.y;
                    if (z == 0) {
                        y0 *= QSCALE; y1 *= QSCALE;
                        store_split2(g_qh, g_ql, off, y0, y1);
                    } else {
                        store_split2(g_kh, g_kl, off, y0, y1);
                    }
                }
            }
}

// Wo GEMM: attn(bf16 split) @ Wo^T -> f32 out (plain layout)
__global__ void __launch_bounds__(256, 2) gemm_out(float* __restrict__ C) {
    extern __shared__ char sm[];
    int m0 = blockIdx.y * 128;
    int n0 = blockIdx.x * 128;
    float acc[2][8][4];
    gemm_core(g_ah, g_al, g_wh[3], g_wl[3], sm, acc, m0, n0);

    int lane = threadIdx.x & 31;
    int wid = threadIdx.x >> 5;
    int warp_m = wid & 3;
    int warp_n = wid >> 2;
#pragma unroll
    for (int mt = 0; mt < 2; mt++)
#pragma unroll
        for (int nt = 0; nt < 8; nt++)
#pragma unroll
            for (int half = 0; half < 2; half++) {
                int m = m0 + warp_m * 32 + mt * 16 + (lane >> 2) + half * 8;
                int n = n0 + warp_n * 64 + nt * 8 + (lane & 3) * 2;
                *(float2*)&C[(size_t)m * D_ + n] =
                    make_float2(acc[mt][nt][half * 2], acc[mt][nt][half * 2 + 1]);
            }
}

// ---------------------------------------------------------------------------
// V: split + transpose to [B,H,64,S]
// ---------------------------------------------------------------------------
__global__ void __launch_bounds__(256) vsplit_t_kernel(
    const float* __restrict__ V, __nv_bfloat16* __restrict__ Vth,
    __nv_bfloat16* __restrict__ Vtl) {
    __shared__ float t[64][65];
    int bh = blockIdx.y;
    int s0 = blockIdx.x * 64;
    int tid = threadIdx.x;
#pragma unroll
    for (int i = 0; i < 16; i++) {
        int e = tid + i * 256;
        int s = e >> 6, d = e & 63;
        t[d][s] = V[((size_t)bh * S_ + s0 + s) * 64 + d];
    }
    __syncthreads();
#pragma unroll
    for (int i = 0; i < 16; i++) {
        int e = tid + i * 256;
        int d = e >> 6, sj = e & 63;
        float val = t[d][sj];
        __nv_bfloat16 h = __float2bfloat16(val);
        size_t o = ((size_t)bh * 64 + d) * S_ + s0 + sj;
        Vth[o] = h;
        Vtl[o] = __float2bfloat16(val - __bfloat162float(h));
    }
}

// ---------------------------------------------------------------------------
// Tensor-core causal flash attention (bf16 split, fp32 accum, poly exp2).
// Heavy q-tiles scheduled first. Epilogue writes bf16 split for Wo GEMM.
// ---------------------------------------------------------------------------
#define AST 144
#define AQ_B (128 * AST)
#define AKV_TILE (64 * AST)
#define AKV_STAGE (4 * AKV_TILE)
#define A_OST (2 * AQ_B)
#define ASMEM (A_OST + 2 * AKV_STAGE)

__global__ void __launch_bounds__(128, 2) attn_mma(
    const __nv_bfloat16* __restrict__ Qh, const __nv_bfloat16* __restrict__ Ql,
    const __nv_bfloat16* __restrict__ Kh, const __nv_bfloat16* __restrict__ Kl,
    const __nv_bfloat16* __restrict__ Vth, const __nv_bfloat16* __restrict__ Vtl,
    __nv_bfloat16* __restrict__ Oh, __nv_bfloat16* __restrict__ Ol) {
    extern __shared__ char sm[];
    uint32_t sb = smem_u32(sm);
    int tid = threadIdx.x;
    int lane = tid & 31;
    int wm = tid >> 5;
    int bh = blockIdx.y;
    int qtile = gridDim.x - 1 - blockIdx.x;  // heavy tiles first
    int q0 = qtile * 128;
    size_t bhS = (size_t)bh * S_;
    int g = lane >> 2, t4 = lane & 3;

    {
        const __nv_bfloat16* sh = Qh + (bhS + q0 + tid) * 64;
        const __nv_bfloat16* sl = Ql + (bhS + q0 + tid) * 64;
        uint32_t dh = sb + tid * AST;
        uint32_t dl = sb + AQ_B + tid * AST;
#pragma unroll
        for (int c = 0; c < 8; c++) {
            CP16(dh + c * 16, sh + c * 8);
            CP16(dl + c * 16, sl + c * 8);
        }
        CP_COMMIT();
    }

    int nblocks = qtile * 2 + 2;

    int krow = tid >> 1;
    int hc = (tid & 1) * 4;
    auto load_kv = [&](int c) {
        uint32_t base = sb + A_OST + (c & 1) * AKV_STAGE;
        int kb = c * 64;
        const __nv_bfloat16* skh = Kh + (bhS + kb + krow) * 64 + hc * 8;
        const __nv_bfloat16* skl = Kl + (bhS + kb + krow) * 64 + hc * 8;
        const __nv_bfloat16* svh = Vth + ((size_t)bh * 64 + krow) * S_ + kb + hc * 8;
        const __nv_bfloat16* svl = Vtl + ((size_t)bh * 64 + krow) * S_ + kb + hc * 8;
        uint32_t d0 = base + krow * AST + hc * 16;
#pragma unroll
        for (int i = 0; i < 4; i++) {
            CP16(d0 + i * 16, skh + i * 8);
            CP16(d0 + AKV_TILE + i * 16, skl + i * 8);
            CP16(d0 + 2 * AKV_TILE + i * 16, svh + i * 8);
            CP16(d0 + 3 * AKV_TILE + i * 16, svl + i * 8);
        }
        CP_COMMIT();
    };
    load_kv(0);
    load_kv(1);

    float o[2][8][4];
    float Sv[2][8][4];
    float mr[2][2], lr[2][2];
#pragma unroll
    for (int mt = 0; mt < 2; mt++) {
#pragma unroll
        for (int nt = 0; nt < 8; nt++)
#pragma unroll
            for (int r = 0; r < 4; r++) o[mt][nt][r] = 0.0f;
        mr[mt][0] = mr[mt][1] = -INFINITY;
        lr[mt][0] = lr[mt][1] = 0.0f;
    }

    for (int c = 0; c < nblocks; c++) {
        if (c == nblocks - 1) CP_WAIT0(); else CP_WAIT1();
        __syncthreads();
        uint32_t base = sb + A_OST + (c & 1) * AKV_STAGE;
        int kb = c * 64;

#pragma unroll
        for (int mt = 0; mt < 2; mt++)
#pragma unroll
            for (int nt = 0; nt < 8; nt++)
#pragma unroll
                for (int r = 0; r < 4; r++) Sv[mt][nt][r] = 0.0f;

#pragma unroll
        for (int ks = 0; ks < 4; ks++) {
            uint32_t ah[2][4], al[2][4];
#pragma unroll
            for (int mt = 0; mt < 2; mt++) {
                uint32_t qa = sb + (wm * 32 + mt * 16 + (lane & 15)) * AST +
                              ks * 32 + ((lane >> 4) << 4);
                LDSM_X4(ah[mt], qa);
                LDSM_X4(al[mt], qa + AQ_B);
            }
#pragma unroll
            for (int ntp = 0; ntp < 4; ntp++) {
                uint32_t ba = base +
                    (ntp * 16 + ((lane >> 4) << 3) + (lane & 7)) * AST +
                    ks * 32 + (((lane >> 3) & 1) << 4);
                uint32_t bhf[4], blf[4];
                LDSM_X4(bhf, ba);
                LDSM_X4(blf, ba + AKV_TILE);
#pragma unroll
                for (int mt = 0; mt < 2; mt++)
#pragma unroll
                    for (int sub = 0; sub < 2; sub++) {
                        int nt = ntp * 2 + sub;
                        MMA_BF16(Sv[mt][nt], ah[mt], bhf[sub * 2], bhf[sub * 2 + 1]);
                        MMA_BF16(Sv[mt][nt], ah[mt], blf[sub * 2], blf[sub * 2 + 1]);
                        MMA_BF16(Sv[mt][nt], al[mt], bhf[sub * 2], bhf[sub * 2 + 1]);
                    }
            }
        }

        if (kb + 63 > q0 + wm * 32) {
#pragma unroll
            for (int mt = 0; mt < 2; mt++)
#pragma unroll
                for (int nt = 0; nt < 8; nt++)
#pragma unroll
                    for (int r = 0; r < 4; r++) {
                        int col = kb + nt * 8 + t4 * 2 + (r & 1);
                        int row = q0 + wm * 32 + mt * 16 + g + (r >> 1) * 8;
                        if (col > row) Sv[mt][nt][r] = -INFINITY;
                    }
        }

#pragma unroll
        for (int mt = 0; mt < 2; mt++)
#pragma unroll
            for (int h = 0; h < 2; h++) {
                float mx = Sv[mt][0][2 * h];
#pragma unroll
                for (int nt = 0; nt < 8; nt++) {
                    mx = fmaxf(mx, Sv[mt][nt][2 * h]);
                    mx = fmaxf(mx, Sv[mt][nt][2 * h + 1]);
                }
                mx = fmaxf(mx, __shfl_xor_sync(0xffffffff, mx, 1));
                mx = fmaxf(mx, __shfl_xor_sync(0xffffffff, mx, 2));
                float mn = fmaxf(mr[mt][h], mx);
                float alpha = exp2p(mr[mt][h] - mn);
                mr[mt][h] = mn;
                float ps = 0.0f;
#pragma unroll
                for (int nt = 0; nt < 8; nt++) {
                    o[mt][nt][2 * h] *= alpha;
                    o[mt][nt][2 * h + 1] *= alpha;
                    float p0 = exp2p(Sv[mt][nt][2 * h] - mn);
                    float p1 = exp2p(Sv[mt][nt][2 * h + 1] - mn);
                    Sv[mt][nt][2 * h] = p0;
                    Sv[mt][nt][2 * h + 1] = p1;
                    ps += p0 + p1;
                }
                ps += __shfl_xor_sync(0xffffffff, ps, 1);
                ps += __shfl_xor_sync(0xffffffff, ps, 2);
                lr[mt][h] = lr[mt][h] * alpha + ps;
            }

#pragma unroll
        for (int ks = 0; ks < 4; ks++) {
            uint32_t ph[2][4], pl[2][4];
#pragma unroll
            for (int mt = 0; mt < 2; mt++)
#pragma unroll
                for (int u = 0; u < 4; u++) {
                    int nt = 2 * ks + (u >> 1);
                    int r0 = (u & 1) * 2;
                    float p0 = Sv[mt][nt][r0], p1 = Sv[mt][nt][r0 + 1];
                    __nv_bfloat162 hh = __floats2bfloat162_rn(p0, p1);
                    ph[mt][u] = *(uint32_t*)&hh;
                    pl[mt][u] = pack_bf2(p0 - __bfloat162float(hh.x),
                                         p1 - __bfloat162float(hh.y));
                }
#pragma unroll
            for (int ntp = 0; ntp < 4; ntp++) {
                uint32_t va = base + 2 * AKV_TILE +
                    (ntp * 16 + ((lane >> 4) << 3) + (lane & 7)) * AST +
                    ks * 32 + (((lane >> 3) & 1) << 4);
                uint32_t bvh[4], bvl[4];
                LDSM_X4(bvh, va);
                LDSM_X4(bvl, va + AKV_TILE);
#pragma unroll
                for (int mt = 0; mt < 2; mt++)
#pragma unroll
                    for (int sub = 0; sub < 2; sub++) {
                        int nt = ntp * 2 + sub;
                        MMA_BF16(o[mt][nt], ph[mt], bvh[sub * 2], bvh[sub * 2 + 1]);
                        MMA_BF16(o[mt][nt], ph[mt], bvl[sub * 2], bvl[sub * 2 + 1]);
                        MMA_BF16(o[mt][nt], pl[mt], bvh[sub * 2], bvh[sub * 2 + 1]);
                    }
            }
        }

        __syncthreads();
        if (c + 2 < nblocks) load_kv(c + 2);
    }

    // Epilogue: normalize + bf16 hi/lo split write to [B,S,H,64]
    int b = bh >> 4, hh = bh & 15;
#pragma unroll
    for (int mt = 0; mt < 2; mt++)
#pragma unroll
        for (int h = 0; h < 2; h++) {
            float inv = 1.0f / lr[mt][h];
            int row = q0 + wm * 32 + mt * 16 + g + 8 * h;
#pragma unroll
            for (int nt = 0; nt < 8; nt++) {
                int d = nt * 8 + t4 * 2;
                size_t off = (((size_t)b * S_ + row) * H_ + hh) * 64 + d;
                store_split2(Oh, Ol, off, o[mt][nt][2 * h] * inv,
                             o[mt][nt][2 * h + 1] * inv);
            }
        }
}

// ---------------------------------------------------------------------------
// Launch
// ---------------------------------------------------------------------------
extern "C" void kernel_launch(void* const* d_in, const int* in_sizes, int n_in,
                              void* d_out, int out_size) {
    const float* x = (const float*)d_in[0];
    const float* Wq = (const float*)d_in[1];
    const float* Wk = (const float*)d_in[2];
    const float* Wv = (const float*)d_in[3];
    const float* Wo = (const float*)d_in[4];
    const int* pos = (const int*)d_in[5];

    float* v;
    __nv_bfloat16 *xh, *xl, *ah, *al, *wh, *wl;
    __nv_bfloat16 *qh, *ql, *kh, *kl, *vth, *vtl;
    cudaGetSymbolAddress((void**)&v, g_v);
    cudaGetSymbolAddress((void**)&xh, g_xh);
    cudaGetSymbolAddress((void**)&xl, g_xl);
    cudaGetSymbolAddress((void**)&ah, g_ah);
    cudaGetSymbolAddress((void**)&al, g_al);
    cudaGetSymbolAddress((void**)&wh, g_wh);
    cudaGetSymbolAddress((void**)&wl, g_wl);
    cudaGetSymbolAddress((void**)&qh, g_qh);
    cudaGetSymbolAddress((void**)&ql, g_ql);
    cudaGetSymbolAddress((void**)&kh, g_kh);
    cudaGetSymbolAddress((void**)&kl, g_kl);
    cudaGetSymbolAddress((void**)&vth, g_vth);
    cudaGetSymbolAddress((void**)&vtl, g_vtl);

    cudaFuncSetAttribute(gemm_qkv,
                         cudaFuncAttributeMaxDynamicSharedMemorySize, GSMEM);
    cudaFuncSetAttribute(gemm_out,
                         cudaFuncAttributeMaxDynamicSharedMemorySize, GSMEM);
    cudaFuncSetAttribute(attn_mma,
                         cudaFuncAttributeMaxDynamicSharedMemorySize, ASMEM);

    sincos_table_kernel<<<(S_ * 32) / 256, 256>>>(pos);

    const int NX = B_ * S_ * D_;  // 4M
    split_kernel<<<NX / 256, 256>>>(x, xh, xl, NX);
    split4_kernel<<<(4 * D_ * D_) / 256, 256>>>(Wq, Wk, Wv, Wo, wh, wl);

    gemm_qkv<<<dim3(D_ / 128, (B_ * S_) / 128, 3), 256, GSMEM>>>(xh, xl);

    vsplit_t_kernel<<<dim3(S_ / 64, B_ * H_), 256>>>(v, vth, vtl);

    attn_mma<<<dim3(S_ / 128, B_ * H_), 128, ASMEM>>>(qh, ql, kh, kl, vth, vtl,
                                                      ah, al);

    gemm_out<<<dim3(D_ / 128, (B_ * S_) / 128), 256, GSMEM>>>((float*)d_out);
}

// round 14
// speedup vs baseline: 1.7806x; 1.0662x over previous
#include <cuda_runtime.h>
#include <cuda_bf16.h>
#include <math.h>
#include <cstdint>

// Problem constants
#define B_ 2
#define S_ 2048
#define D_ 1024
#define H_ 16
#define DK_ 64

// ---------------------------------------------------------------------------
// Scratch (__device__ globals; no allocation allowed)
// ---------------------------------------------------------------------------
__device__ float g_v[B_ * S_ * D_];  // [B,H,S,64] f32 (pre-transpose V)
__device__ float2 g_sc[S_ * 32];

// bf16 split buffers
__device__ __nv_bfloat16 g_xh[B_ * S_ * D_];
__device__ __nv_bfloat16 g_xl[B_ * S_ * D_];
__device__ __nv_bfloat16 g_ah[B_ * S_ * D_];   // attn out hi [B,S,H,64]
__device__ __nv_bfloat16 g_al[B_ * S_ * D_];
__device__ __nv_bfloat16 g_wh[4][D_ * D_];
__device__ __nv_bfloat16 g_wl[4][D_ * D_];

__device__ __nv_bfloat16 g_qh[B_ * S_ * D_];   // [B,H,S,64], rope+scaled
__device__ __nv_bfloat16 g_ql[B_ * S_ * D_];
__device__ __nv_bfloat16 g_kh[B_ * S_ * D_];   // [B,H,S,64], rope
__device__ __nv_bfloat16 g_kl[B_ * S_ * D_];
__device__ __nv_bfloat16 g_vth[B_ * S_ * D_];  // [B,H,64,S]
__device__ __nv_bfloat16 g_vtl[B_ * S_ * D_];

// ---------------------------------------------------------------------------
// PTX helpers (baseline ISA: mma.sync / ldmatrix / cp.async — sm_103-safe)
// ---------------------------------------------------------------------------
__device__ __forceinline__ uint32_t smem_u32(const void* p) {
    uint32_t a;
    asm("{ .reg .u64 t; cvta.to.shared.u64 t, %1; cvt.u32.u64 %0, t; }"
        : "=r"(a) : "l"(p));
    return a;
}

#define CP16(dst, src) \
    asm volatile("cp.async.cg.shared.global [%0], [%1], 16;" \
                 :: "r"(dst), "l"(src))
#define CP_COMMIT() asm volatile("cp.async.commit_group;")
#define CP_WAIT2() asm volatile("cp.async.wait_group 2;")
#define CP_WAIT1() asm volatile("cp.async.wait_group 1;")
#define CP_WAIT0() asm volatile("cp.async.wait_group 0;")

#define LDSM_X4(r, a)                                                       \
    asm volatile("ldmatrix.sync.aligned.m8n8.x4.shared.b16 "                \
                 "{%0,%1,%2,%3}, [%4];"                                     \
                 : "=r"((r)[0]), "=r"((r)[1]), "=r"((r)[2]), "=r"((r)[3])   \
                 : "r"(a))

#define MMA_BF16(d, a, b0, b1)                                              \
    asm volatile("mma.sync.aligned.m16n8k16.row.col.f32.bf16.bf16.f32 "     \
                 "{%0,%1,%2,%3},{%4,%5,%6,%7},{%8,%9},{%0,%1,%2,%3};"       \
                 : "+f"((d)[0]), "+f"((d)[1]), "+f"((d)[2]), "+f"((d)[3])   \
                 : "r"((a)[0]), "r"((a)[1]), "r"((a)[2]), "r"((a)[3]),      \
                   "r"(b0), "r"(b1))

// FFMA-only exp2 for t <= 0 (deg-6 poly, rel err ~1.2e-7)
__device__ __forceinline__ float exp2p(float t) {
    t = fmaxf(t, -80.0f);
    float y = __fadd_rn(t, 12582912.0f);
    int n = __float_as_int(y) - 0x4B400000;
    float f = __fsub_rn(t, __fsub_rn(y, 12582912.0f));
    float p = 1.54035304e-4f;
    p = fmaf(p, f, 1.33335581e-3f);
    p = fmaf(p, f, 9.61812911e-3f);
    p = fmaf(p, f, 5.55041087e-2f);
    p = fmaf(p, f, 2.40226507e-1f);
    p = fmaf(p, f, 6.93147181e-1f);
    p = fmaf(p, f, 1.0f);
    return __int_as_float(__float_as_int(p) + (n << 23));
}

__device__ __forceinline__ uint32_t pack_bf2(float lo, float hi) {
    __nv_bfloat162 h = __floats2bfloat162_rn(lo, hi);
    return *(uint32_t*)&h;
}

// Write an fp32 pair as (hi, lo) bf16x2 pairs
__device__ __forceinline__ void store_split2(__nv_bfloat16* Hp,
                                             __nv_bfloat16* Lp, size_t off,
                                             float v0, float v1) {
    __nv_bfloat162 hh = __floats2bfloat162_rn(v0, v1);
    *(__nv_bfloat162*)(Hp + off) = hh;
    __nv_bfloat162 ll = __floats2bfloat162_rn(v0 - __bfloat162float(hh.x),
                                              v1 - __bfloat162float(hh.y));
    *(__nv_bfloat162*)(Lp + off) = ll;
}

// 64B-row swizzle for GEMM smem tiles: rows of 4x16B chunks.
// Bijective over each 8-row 512B group -> conflict-free stores and ldsm.
__device__ __forceinline__ uint32_t swz64(uint32_t row, uint32_t chunk) {
    return row * 64 + ((chunk ^ ((row >> 1) & 3)) << 4);
}

// ---------------------------------------------------------------------------
// fp32 -> (hi, lo) bf16 split (x input)
// ---------------------------------------------------------------------------
__global__ void split_kernel(const float* __restrict__ in,
                             __nv_bfloat16* __restrict__ hi,
                             __nv_bfloat16* __restrict__ lo, int n) {
    int i = blockIdx.x * blockDim.x + threadIdx.x;
    if (i >= n) return;
    float v = in[i];
    __nv_bfloat16 h = __float2bfloat16(v);
    hi[i] = h;
    lo[i] = __float2bfloat16(v - __bfloat162float(h));
}

// All 4 weights in one launch (g_wh/g_wl are [4][NW] contiguous)
__global__ void split4_kernel(const float* __restrict__ w0,
                              const float* __restrict__ w1,
                              const float* __restrict__ w2,
                              const float* __restrict__ w3,
                              __nv_bfloat16* __restrict__ hi,
                              __nv_bfloat16* __restrict__ lo) {
    int i = blockIdx.x * blockDim.x + threadIdx.x;
    int sel = i >> 20;  // NW = 1<<20
    int off = i & ((1 << 20) - 1);
    const float* src = (sel == 0) ? w0 : (sel == 1) ? w1 : (sel == 2) ? w2 : w3;
    float v = src[off];
    __nv_bfloat16 h = __float2bfloat16(v);
    hi[i] = h;
    lo[i] = __float2bfloat16(v - __bfloat162float(h));
}

// ---------------------------------------------------------------------------
// sin/cos table (exact range reduction)
// ---------------------------------------------------------------------------
__global__ void sincos_table_kernel(const int* __restrict__ pos) {
    int idx = blockIdx.x * blockDim.x + threadIdx.x;
    if (idx >= S_ * 32) return;
    int s = idx >> 5;
    int p = idx & 31;
    float invf = (float)exp2(-(double)p * 0.4152410118609203);
    float ang = (float)pos[s] * invf;
    double a = (double)ang;
    double kq = floor(a * 0.15915494309189535);
    float r = (float)(a - kq * 6.283185307179586);
    float sn, cs;
    sincosf(r, &sn, &cs);
    g_sc[idx] = make_float2(sn, cs);
}

// ---------------------------------------------------------------------------
// GEMM core: 3-stage cp.async pipeline, swizzled 64B rows, 1 sync per chunk.
// ---------------------------------------------------------------------------
#define NCHUNK 32
#define GTILE 8192              // 128 rows x 64B
#define GSTAGE (4 * GTILE)      // Ah, Al, Bh, Bl
#define GSMEM (3 * GSTAGE)      // 98304

__device__ __forceinline__ void gemm_core(
    const __nv_bfloat16* __restrict__ Ah, const __nv_bfloat16* __restrict__ Al,
    const __nv_bfloat16* __restrict__ Bh, const __nv_bfloat16* __restrict__ Bl,
    char* sm, float acc[2][8][4], int m0, int n0) {
    uint32_t sb = smem_u32(sm);
    int tid = threadIdx.x;
    int lane = tid & 31;
    int wid = tid >> 5;
    int warp_m = wid & 3;
    int warp_n = wid >> 2;

    const __nv_bfloat16* gsrc[4] = {
        Ah + (size_t)m0 * D_, Al + (size_t)m0 * D_,
        Bh + (size_t)n0 * D_, Bl + (size_t)n0 * D_};

    int ldrow = tid >> 2;  // 0..63
    int ldc16 = tid & 3;   // 16B chunk in 64B row

    auto load_stage = [&](int c) {
        uint32_t dbase = sb + (c % 3) * GSTAGE;
#pragma unroll
        for (int op = 0; op < 4; op++) {
#pragma unroll
            for (int i = 0; i < 2; i++) {
                int row = ldrow + i * 64;
                uint32_t dst = dbase + op * GTILE + swz64(row, ldc16);
                const __nv_bfloat16* src =
                    gsrc[op] + (size_t)row * D_ + c * 32 + ldc16 * 8;
                CP16(dst, src);
            }
        }
        CP_COMMIT();
    };

    load_stage(0);
    load_stage(1);

#pragma unroll
    for (int mt = 0; mt < 2; mt++)
#pragma unroll
        for (int nt = 0; nt < 8; nt++)
#pragma unroll
            for (int r = 0; r < 4; r++) acc[mt][nt][r] = 0.0f;

    for (int c = 0; c < NCHUNK; c++) {
        if (c < NCHUNK - 1) CP_WAIT1(); else CP_WAIT0();
        __syncthreads();
        if (c + 2 < NCHUNK) load_stage(c + 2);
        uint32_t base = sb + (c % 3) * GSTAGE;

#pragma unroll
        for (int s = 0; s < 2; s++) {
            uint32_t ah[2][4], al[2][4];
#pragma unroll
            for (int mt = 0; mt < 2; mt++) {
                uint32_t arow = warp_m * 32 + mt * 16 + (lane & 15);
                uint32_t aoff = swz64(arow, 2 * s + (lane >> 4));
                LDSM_X4(ah[mt], base + aoff);
                LDSM_X4(al[mt], base + GTILE + aoff);
            }
            uint32_t bh[4][4], bl[4][4];
#pragma unroll
            for (int p = 0; p < 4; p++) {
                uint32_t brow = warp_n * 64 + p * 16 + ((lane >> 4) << 3) + (lane & 7);
                uint32_t boff = swz64(brow, 2 * s + ((lane >> 3) & 1));
                LDSM_X4(bh[p], base + 2 * GTILE + boff);
                LDSM_X4(bl[p], base + 3 * GTILE + boff);
            }
#pragma unroll
            for (int mt = 0; mt < 2; mt++)
#pragma unroll
                for (int nt = 0; nt < 8; nt++) {
                    int p = nt >> 1, hf = (nt & 1) * 2;
                    MMA_BF16(acc[mt][nt], ah[mt], bh[p][hf], bh[p][hf + 1]);
                    MMA_BF16(acc[mt][nt], ah[mt], bl[p][hf], bl[p][hf + 1]);
                    MMA_BF16(acc[mt][nt], al[mt], bh[p][hf], bh[p][hf + 1]);
                }
        }
    }
}

__global__ void __launch_bounds__(256, 2) gemm_qkv(
    const __nv_bfloat16* __restrict__ Xh, const __nv_bfloat16* __restrict__ Xl) {
    extern __shared__ char sm[];
    int z = blockIdx.z;
    int m0 = blockIdx.y * 128;
    int n0 = blockIdx.x * 128;

    float acc[2][8][4];
    gemm_core(Xh, Xl, g_wh[z], g_wl[z], sm, acc, m0, n0);

    int lane = threadIdx.x & 31;
    int wid = threadIdx.x >> 5;
    int warp_m = wid & 3;
    int warp_n = wid >> 2;
    const float QSCALE = 0.125f * 1.4426950408889634f;

#pragma unroll
    for (int mt = 0; mt < 2; mt++)
#pragma unroll
        for (int nt = 0; nt < 8; nt++)
#pragma unroll
            for (int half = 0; half < 2; half++) {
                int m = m0 + warp_m * 32 + mt * 16 + (lane >> 2) + half * 8;
                int n = n0 + warp_n * 64 + nt * 8 + (lane & 3) * 2;
                float v0 = acc[mt][nt][half * 2];
                float v1 = acc[mt][nt][half * 2 + 1];
                int b = m >> 11, s = m & (S_ - 1), h = n >> 6, d = n & 63;
                size_t off = ((((size_t)b * H_ + h) * S_ + s) << 6) + d;
                if (z == 2) {
                    *(float2*)&g_v[off] = make_float2(v0, v1);
                } else {
                    float2 sc = g_sc[(s << 5) | (d >> 1)];  // d even
                    float y0 = v0 * sc.y - v1 * sc.x;
                    float y1 = v0 * sc.x + v1 * sc.y;
                    if (z == 0) {
                        y0 *= QSCALE; y1 *= QSCALE;
                        store_split2(g_qh, g_ql, off, y0, y1);
                    } else {
                        store_split2(g_kh, g_kl, off, y0, y1);
                    }
                }
            }
}

// Wo GEMM: attn(bf16 split) @ Wo^T -> f32 out (plain layout)
__global__ void __launch_bounds__(256, 2) gemm_out(float* __restrict__ C) {
    extern __shared__ char sm[];
    int m0 = blockIdx.y * 128;
    int n0 = blockIdx.x * 128;
    float acc[2][8][4];
    gemm_core(g_ah, g_al, g_wh[3], g_wl[3], sm, acc, m0, n0);

    int lane = threadIdx.x & 31;
    int wid = threadIdx.x >> 5;
    int warp_m = wid & 3;
    int warp_n = wid >> 2;
#pragma unroll
    for (int mt = 0; mt < 2; mt++)
#pragma unroll
        for (int nt = 0; nt < 8; nt++)
#pragma unroll
            for (int half = 0; half < 2; half++) {
                int m = m0 + warp_m * 32 + mt * 16 + (lane >> 2) + half * 8;
                int n = n0 + warp_n * 64 + nt * 8 + (lane & 3) * 2;
                *(float2*)&C[(size_t)m * D_ + n] =
                    make_float2(acc[mt][nt][half * 2], acc[mt][nt][half * 2 + 1]);
            }
}

// ---------------------------------------------------------------------------
// V: split + transpose to [B,H,64,S]
// ---------------------------------------------------------------------------
__global__ void __launch_bounds__(256) vsplit_t_kernel(
    const float* __restrict__ V, __nv_bfloat16* __restrict__ Vth,
    __nv_bfloat16* __restrict__ Vtl) {
    __shared__ float t[64][65];
    int bh = blockIdx.y;
    int s0 = blockIdx.x * 64;
    int tid = threadIdx.x;
#pragma unroll
    for (int i = 0; i < 16; i++) {
        int e = tid + i * 256;
        int s = e >> 6, d = e & 63;
        t[d][s] = V[((size_t)bh * S_ + s0 + s) * 64 + d];
    }
    __syncthreads();
#pragma unroll
    for (int i = 0; i < 16; i++) {
        int e = tid + i * 256;
        int d = e >> 6, sj = e & 63;
        float val = t[d][sj];
        __nv_bfloat16 h = __float2bfloat16(val);
        size_t o = ((size_t)bh * 64 + d) * S_ + s0 + sj;
        Vth[o] = h;
        Vtl[o] = __float2bfloat16(val - __bfloat162float(h));
    }
}

// ---------------------------------------------------------------------------
// Tensor-core causal flash attention. Q fragments hoisted to registers
// (constant across KV blocks) — removes 16 ldsm.x4/warp/block.
// ---------------------------------------------------------------------------
#define AST 144
#define AQ_B (128 * AST)
#define AKV_TILE (64 * AST)
#define AKV_STAGE (4 * AKV_TILE)
#define A_OST (2 * AQ_B)
#define ASMEM (A_OST + 2 * AKV_STAGE)

__global__ void __launch_bounds__(128, 2) attn_mma(
    const __nv_bfloat16* __restrict__ Qh, const __nv_bfloat16* __restrict__ Ql,
    const __nv_bfloat16* __restrict__ Kh, const __nv_bfloat16* __restrict__ Kl,
    const __nv_bfloat16* __restrict__ Vth, const __nv_bfloat16* __restrict__ Vtl,
    __nv_bfloat16* __restrict__ Oh, __nv_bfloat16* __restrict__ Ol) {
    extern __shared__ char sm[];
    uint32_t sb = smem_u32(sm);
    int tid = threadIdx.x;
    int lane = tid & 31;
    int wm = tid >> 5;
    int bh = blockIdx.y;
    int qtile = gridDim.x - 1 - blockIdx.x;  // heavy tiles first
    int q0 = qtile * 128;
    size_t bhS = (size_t)bh * S_;
    int g = lane >> 2, t4 = lane & 3;

    // Q copy (group 0)
    {
        const __nv_bfloat16* sh = Qh + (bhS + q0 + tid) * 64;
        const __nv_bfloat16* sl = Ql + (bhS + q0 + tid) * 64;
        uint32_t dh = sb + tid * AST;
        uint32_t dl = sb + AQ_B + tid * AST;
#pragma unroll
        for (int c = 0; c < 8; c++) {
            CP16(dh + c * 16, sh + c * 8);
            CP16(dl + c * 16, sl + c * 8);
        }
        CP_COMMIT();
    }

    int nblocks = qtile * 2 + 2;

    int krow = tid >> 1;
    int hc = (tid & 1) * 4;
    auto load_kv = [&](int c) {
        uint32_t base = sb + A_OST + (c & 1) * AKV_STAGE;
        int kb = c * 64;
        const __nv_bfloat16* skh = Kh + (bhS + kb + krow) * 64 + hc * 8;
        const __nv_bfloat16* skl = Kl + (bhS + kb + krow) * 64 + hc * 8;
        const __nv_bfloat16* svh = Vth + ((size_t)bh * 64 + krow) * S_ + kb + hc * 8;
        const __nv_bfloat16* svl = Vtl + ((size_t)bh * 64 + krow) * S_ + kb + hc * 8;
        uint32_t d0 = base + krow * AST + hc * 16;
#pragma unroll
        for (int i = 0; i < 4; i++) {
            CP16(d0 + i * 16, skh + i * 8);
            CP16(d0 + AKV_TILE + i * 16, skl + i * 8);
            CP16(d0 + 2 * AKV_TILE + i * 16, svh + i * 8);
            CP16(d0 + 3 * AKV_TILE + i * 16, svl + i * 8);
        }
        CP_COMMIT();
    };
    load_kv(0);   // group 1
    load_kv(1);   // group 2

    // Q fragments -> registers, once (Q group done when <=2 outstanding)
    CP_WAIT2();
    __syncthreads();
    uint32_t qfh[2][4][4], qfl[2][4][4];
#pragma unroll
    for (int mt = 0; mt < 2; mt++)
#pragma unroll
        for (int ks = 0; ks < 4; ks++) {
            uint32_t qa = sb + (wm * 32 + mt * 16 + (lane & 15)) * AST +
                          ks * 32 + ((lane >> 4) << 4);
            LDSM_X4(qfh[mt][ks], qa);
            LDSM_X4(qfl[mt][ks], qa + AQ_B);
        }

    float o[2][8][4];
    float Sv[2][8][4];
    float mr[2][2], lr[2][2];
#pragma unroll
    for (int mt = 0; mt < 2; mt++) {
#pragma unroll
        for (int nt = 0; nt < 8; nt++)
#pragma unroll
            for (int r = 0; r < 4; r++) o[mt][nt][r] = 0.0f;
        mr[mt][0] = mr[mt][1] = -INFINITY;
        lr[mt][0] = lr[mt][1] = 0.0f;
    }

    for (int c = 0; c < nblocks; c++) {
        if (c == nblocks - 1) CP_WAIT0(); else CP_WAIT1();
        __syncthreads();
        uint32_t base = sb + A_OST + (c & 1) * AKV_STAGE;
        int kb = c * 64;

#pragma unroll
        for (int mt = 0; mt < 2; mt++)
#pragma unroll
            for (int nt = 0; nt < 8; nt++)
#pragma unroll
                for (int r = 0; r < 4; r++) Sv[mt][nt][r] = 0.0f;

#pragma unroll
        for (int ks = 0; ks < 4; ks++) {
#pragma unroll
            for (int ntp = 0; ntp < 4; ntp++) {
                uint32_t ba = base +
                    (ntp * 16 + ((lane >> 4) << 3) + (lane & 7)) * AST +
                    ks * 32 + (((lane >> 3) & 1) << 4);
                uint32_t bhf[4], blf[4];
                LDSM_X4(bhf, ba);
                LDSM_X4(blf, ba + AKV_TILE);
#pragma unroll
                for (int mt = 0; mt < 2; mt++)
#pragma unroll
                    for (int sub = 0; sub < 2; sub++) {
                        int nt = ntp * 2 + sub;
                        MMA_BF16(Sv[mt][nt], qfh[mt][ks], bhf[sub * 2], bhf[sub * 2 + 1]);
                        MMA_BF16(Sv[mt][nt], qfh[mt][ks], blf[sub * 2], blf[sub * 2 + 1]);
                        MMA_BF16(Sv[mt][nt], qfl[mt][ks], bhf[sub * 2], bhf[sub * 2 + 1]);
                    }
            }
        }

        if (kb + 63 > q0 + wm * 32) {
#pragma unroll
            for (int mt = 0; mt < 2; mt++)
#pragma unroll
                for (int nt = 0; nt < 8; nt++)
#pragma unroll
                    for (int r = 0; r < 4; r++) {
                        int col = kb + nt * 8 + t4 * 2 + (r & 1);
                        int row = q0 + wm * 32 + mt * 16 + g + (r >> 1) * 8;
                        if (col > row) Sv[mt][nt][r] = -INFINITY;
                    }
        }

#pragma unroll
        for (int mt = 0; mt < 2; mt++)
#pragma unroll
            for (int h = 0; h < 2; h++) {
                float mx = Sv[mt][0][2 * h];
#pragma unroll
                for (int nt = 0; nt < 8; nt++) {
                    mx = fmaxf(mx, Sv[mt][nt][2 * h]);
                    mx = fmaxf(mx, Sv[mt][nt][2 * h + 1]);
                }
                mx = fmaxf(mx, __shfl_xor_sync(0xffffffff, mx, 1));
                mx = fmaxf(mx, __shfl_xor_sync(0xffffffff, mx, 2));
                float mn = fmaxf(mr[mt][h], mx);
                float alpha = exp2p(mr[mt][h] - mn);
                mr[mt][h] = mn;
                float ps = 0.0f;
#pragma unroll
                for (int nt = 0; nt < 8; nt++) {
                    o[mt][nt][2 * h] *= alpha;
                    o[mt][nt][2 * h + 1] *= alpha;
                    float p0 = exp2p(Sv[mt][nt][2 * h] - mn);
                    float p1 = exp2p(Sv[mt][nt][2 * h + 1] - mn);
                    Sv[mt][nt][2 * h] = p0;
                    Sv[mt][nt][2 * h + 1] = p1;
                    ps += p0 + p1;
                }
                ps += __shfl_xor_sync(0xffffffff, ps, 1);
                ps += __shfl_xor_sync(0xffffffff, ps, 2);
                lr[mt][h] = lr[mt][h] * alpha + ps;
            }

#pragma unroll
        for (int ks = 0; ks < 4; ks++) {
            uint32_t ph[2][4], pl[2][4];
#pragma unroll
            for (int mt = 0; mt < 2; mt++)
#pragma unroll
                for (int u = 0; u < 4; u++) {
                    int nt = 2 * ks + (u >> 1);
                    int r0 = (u & 1) * 2;
                    float p0 = Sv[mt][nt][r0], p1 = Sv[mt][nt][r0 + 1];
                    __nv_bfloat162 hh = __floats2bfloat162_rn(p0, p1);
                    ph[mt][u] = *(uint32_t*)&hh;
                    pl[mt][u] = pack_bf2(p0 - __bfloat162float(hh.x),
                                         p1 - __bfloat162float(hh.y));
                }
#pragma unroll
            for (int ntp = 0; ntp < 4; ntp++) {
                uint32_t va = base + 2 * AKV_TILE +
                    (ntp * 16 + ((lane >> 4) << 3) + (lane & 7)) * AST +
                    ks * 32 + (((lane >> 3) & 1) << 4);
                uint32_t bvh[4], bvl[4];
                LDSM_X4(bvh, va);
                LDSM_X4(bvl, va + AKV_TILE);
#pragma unroll
                for (int mt = 0; mt < 2; mt++)
#pragma unroll
                    for (int sub = 0; sub < 2; sub++) {
                        int nt = ntp * 2 + sub;
                        MMA_BF16(o[mt][nt], ph[mt], bvh[sub * 2], bvh[sub * 2 + 1]);
                        MMA_BF16(o[mt][nt], ph[mt], bvl[sub * 2], bvl[sub * 2 + 1]);
                        MMA_BF16(o[mt][nt], pl[mt], bvh[sub * 2], bvh[sub * 2 + 1]);
                    }
            }
        }

        __syncthreads();
        if (c + 2 < nblocks) load_kv(c + 2);
    }

    // Epilogue: normalize + bf16 hi/lo split write to [B,S,H,64]
    int b = bh >> 4, hh = bh & 15;
#pragma unroll
    for (int mt = 0; mt < 2; mt++)
#pragma unroll
        for (int h = 0; h < 2; h++) {
            float inv = 1.0f / lr[mt][h];
            int row = q0 + wm * 32 + mt * 16 + g + 8 * h;
#pragma unroll
            for (int nt = 0; nt < 8; nt++) {
                int d = nt * 8 + t4 * 2;
                size_t off = (((size_t)b * S_ + row) * H_ + hh) * 64 + d;
                store_split2(Oh, Ol, off, o[mt][nt][2 * h] * inv,
                             o[mt][nt][2 * h + 1] * inv);
            }
        }
}

// ---------------------------------------------------------------------------
// Launch
// ---------------------------------------------------------------------------
extern "C" void kernel_launch(void* const* d_in, const int* in_sizes, int n_in,
                              void* d_out, int out_size) {
    const float* x = (const float*)d_in[0];
    const float* Wq = (const float*)d_in[1];
    const float* Wk = (const float*)d_in[2];
    const float* Wv = (const float*)d_in[3];
    const float* Wo = (const float*)d_in[4];
    const int* pos = (const int*)d_in[5];

    float* v;
    __nv_bfloat16 *xh, *xl, *ah, *al, *wh, *wl;
    __nv_bfloat16 *qh, *ql, *kh, *kl, *vth, *vtl;
    cudaGetSymbolAddress((void**)&v, g_v);
    cudaGetSymbolAddress((void**)&xh, g_xh);
    cudaGetSymbolAddress((void**)&xl, g_xl);
    cudaGetSymbolAddress((void**)&ah, g_ah);
    cudaGetSymbolAddress((void**)&al, g_al);
    cudaGetSymbolAddress((void**)&wh, g_wh);
    cudaGetSymbolAddress((void**)&wl, g_wl);
    cudaGetSymbolAddress((void**)&qh, g_qh);
    cudaGetSymbolAddress((void**)&ql, g_ql);
    cudaGetSymbolAddress((void**)&kh, g_kh);
    cudaGetSymbolAddress((void**)&kl, g_kl);
    cudaGetSymbolAddress((void**)&vth, g_vth);
    cudaGetSymbolAddress((void**)&vtl, g_vtl);

    cudaFuncSetAttribute(gemm_qkv,
                         cudaFuncAttributeMaxDynamicSharedMemorySize, GSMEM);
    cudaFuncSetAttribute(gemm_out,
                         cudaFuncAttributeMaxDynamicSharedMemorySize, GSMEM);
    cudaFuncSetAttribute(attn_mma,
                         cudaFuncAttributeMaxDynamicSharedMemorySize, ASMEM);

    sincos_table_kernel<<<(S_ * 32) / 256, 256>>>(pos);

    const int NX = B_ * S_ * D_;  // 4M
    split_kernel<<<NX / 256, 256>>>(x, xh, xl, NX);
    split4_kernel<<<(4 * D_ * D_) / 256, 256>>>(Wq, Wk, Wv, Wo, wh, wl);

    gemm_qkv<<<dim3(D_ / 128, (B_ * S_) / 128, 3), 256, GSMEM>>>(xh, xl);

    vsplit_t_kernel<<<dim3(S_ / 64, B_ * H_), 256>>>(v, vth, vtl);

    attn_mma<<<dim3(S_ / 128, B_ * H_), 128, ASMEM>>>(qh, ql, kh, kl, vth, vtl,
                                                      ah, al);

    gemm_out<<<dim3(D_ / 128, (B_ * S_) / 128), 256, GSMEM>>>((float*)d_out);
}

// round 15
// speedup vs baseline: 1.8897x; 1.0613x over previous
#include <cuda_runtime.h>
#include <cuda_bf16.h>
#include <cuda_fp16.h>
#include <math.h>
#include <cstdint>

// Problem constants
#define B_ 2
#define S_ 2048
#define D_ 1024
#define H_ 16
#define DK_ 64

// ---------------------------------------------------------------------------
// Scratch (__device__ globals; no allocation allowed)
// ---------------------------------------------------------------------------
__device__ float g_v[B_ * S_ * D_];  // [B,H,S,64] f32 (pre-transpose V)
__device__ float2 g_sc[S_ * 32];

// bf16 split buffers
__device__ __nv_bfloat16 g_xh[B_ * S_ * D_];
__device__ __nv_bfloat16 g_xl[B_ * S_ * D_];
__device__ __nv_bfloat16 g_ah[B_ * S_ * D_];   // attn out hi [B,S,H,64]
__device__ __nv_bfloat16 g_al[B_ * S_ * D_];
__device__ __nv_bfloat16 g_wh[4][D_ * D_];
__device__ __nv_bfloat16 g_wl[4][D_ * D_];

__device__ __nv_bfloat16 g_qh[B_ * S_ * D_];   // [B,H,S,64], rope+scaled
__device__ __nv_bfloat16 g_ql[B_ * S_ * D_];
__device__ __nv_bfloat16 g_kh[B_ * S_ * D_];   // [B,H,S,64], rope
__device__ __nv_bfloat16 g_kl[B_ * S_ * D_];
__device__ __half g_vth[B_ * S_ * D_];         // [B,H,64,S] fp16 hi
__device__ __half g_vtl[B_ * S_ * D_];         // [B,H,64,S] fp16 lo

// ---------------------------------------------------------------------------
// PTX helpers (baseline ISA: mma.sync / ldmatrix / cp.async — sm_103-safe)
// ---------------------------------------------------------------------------
__device__ __forceinline__ uint32_t smem_u32(const void* p) {
    uint32_t a;
    asm("{ .reg .u64 t; cvta.to.shared.u64 t, %1; cvt.u32.u64 %0, t; }"
        : "=r"(a) : "l"(p));
    return a;
}

#define CP16(dst, src) \
    asm volatile("cp.async.cg.shared.global [%0], [%1], 16;" \
                 :: "r"(dst), "l"(src))
#define CP_COMMIT() asm volatile("cp.async.commit_group;")
#define CP_WAIT2() asm volatile("cp.async.wait_group 2;")
#define CP_WAIT1() asm volatile("cp.async.wait_group 1;")
#define CP_WAIT0() asm volatile("cp.async.wait_group 0;")

#define LDSM_X4(r, a)                                                       \
    asm volatile("ldmatrix.sync.aligned.m8n8.x4.shared.b16 "                \
                 "{%0,%1,%2,%3}, [%4];"                                     \
                 : "=r"((r)[0]), "=r"((r)[1]), "=r"((r)[2]), "=r"((r)[3])   \
                 : "r"(a))

#define MMA_BF16(d, a, b0, b1)                                              \
    asm volatile("mma.sync.aligned.m16n8k16.row.col.f32.bf16.bf16.f32 "     \
                 "{%0,%1,%2,%3},{%4,%5,%6,%7},{%8,%9},{%0,%1,%2,%3};"       \
                 : "+f"((d)[0]), "+f"((d)[1]), "+f"((d)[2]), "+f"((d)[3])   \
                 : "r"((a)[0]), "r"((a)[1]), "r"((a)[2]), "r"((a)[3]),      \
                   "r"(b0), "r"(b1))

#define MMA_FP16(d, a, b0, b1)                                              \
    asm volatile("mma.sync.aligned.m16n8k16.row.col.f32.f16.f16.f32 "      \
                 "{%0,%1,%2,%3},{%4,%5,%6,%7},{%8,%9},{%0,%1,%2,%3};"       \
                 : "+f"((d)[0]), "+f"((d)[1]), "+f"((d)[2]), "+f"((d)[3])   \
                 : "r"((a)[0]), "r"((a)[1]), "r"((a)[2]), "r"((a)[3]),      \
                   "r"(b0), "r"(b1))

// FFMA-only exp2 for t <= 0 (deg-6 poly, rel err ~1.2e-7)
__device__ __forceinline__ float exp2p(float t) {
    t = fmaxf(t, -80.0f);
    float y = __fadd_rn(t, 12582912.0f);
    int n = __float_as_int(y) - 0x4B400000;
    float f = __fsub_rn(t, __fsub_rn(y, 12582912.0f));
    float p = 1.54035304e-4f;
    p = fmaf(p, f, 1.33335581e-3f);
    p = fmaf(p, f, 9.61812911e-3f);
    p = fmaf(p, f, 5.55041087e-2f);
    p = fmaf(p, f, 2.40226507e-1f);
    p = fmaf(p, f, 6.93147181e-1f);
    p = fmaf(p, f, 1.0f);
    return __int_as_float(__float_as_int(p) + (n << 23));
}

// Write an fp32 pair as (hi, lo) bf16x2 pairs
__device__ __forceinline__ void store_split2(__nv_bfloat16* Hp,
                                             __nv_bfloat16* Lp, size_t off,
                                             float v0, float v1) {
    __nv_bfloat162 hh = __floats2bfloat162_rn(v0, v1);
    *(__nv_bfloat162*)(Hp + off) = hh;
    __nv_bfloat162 ll = __floats2bfloat162_rn(v0 - __bfloat162float(hh.x),
                                              v1 - __bfloat162float(hh.y));
    *(__nv_bfloat162*)(Lp + off) = ll;
}

// 64B-row swizzle for GEMM smem tiles: rows of 4x16B chunks.
__device__ __forceinline__ uint32_t swz64(uint32_t row, uint32_t chunk) {
    return row * 64 + ((chunk ^ ((row >> 1) & 3)) << 4);
}

// ---------------------------------------------------------------------------
// fp32 -> (hi, lo) bf16 split (x input)
// ---------------------------------------------------------------------------
__global__ void split_kernel(const float* __restrict__ in,
                             __nv_bfloat16* __restrict__ hi,
                             __nv_bfloat16* __restrict__ lo, int n) {
    int i = blockIdx.x * blockDim.x + threadIdx.x;
    if (i >= n) return;
    float v = in[i];
    __nv_bfloat16 h = __float2bfloat16(v);
    hi[i] = h;
    lo[i] = __float2bfloat16(v - __bfloat162float(h));
}

// All 4 weights in one launch (g_wh/g_wl are [4][NW] contiguous)
__global__ void split4_kernel(const float* __restrict__ w0,
                              const float* __restrict__ w1,
                              const float* __restrict__ w2,
                              const float* __restrict__ w3,
                              __nv_bfloat16* __restrict__ hi,
                              __nv_bfloat16* __restrict__ lo) {
    int i = blockIdx.x * blockDim.x + threadIdx.x;
    int sel = i >> 20;  // NW = 1<<20
    int off = i & ((1 << 20) - 1);
    const float* src = (sel == 0) ? w0 : (sel == 1) ? w1 : (sel == 2) ? w2 : w3;
    float v = src[off];
    __nv_bfloat16 h = __float2bfloat16(v);
    hi[i] = h;
    lo[i] = __float2bfloat16(v - __bfloat162float(h));
}

// ---------------------------------------------------------------------------
// sin/cos table (exact range reduction)
// ---------------------------------------------------------------------------
__global__ void sincos_table_kernel(const int* __restrict__ pos) {
    int idx = blockIdx.x * blockDim.x + threadIdx.x;
    if (idx >= S_ * 32) return;
    int s = idx >> 5;
    int p = idx & 31;
    float invf = (float)exp2(-(double)p * 0.4152410118609203);
    float ang = (float)pos[s] * invf;
    double a = (double)ang;
    double kq = floor(a * 0.15915494309189535);
    float r = (float)(a - kq * 6.283185307179586);
    float sn, cs;
    sincosf(r, &sn, &cs);
    g_sc[idx] = make_float2(sn, cs);
}

// ---------------------------------------------------------------------------
// GEMM core: 3-stage cp.async pipeline, swizzled 64B rows, 1 sync per chunk.
// ---------------------------------------------------------------------------
#define NCHUNK 32
#define GTILE 8192              // 128 rows x 64B
#define GSTAGE (4 * GTILE)      // Ah, Al, Bh, Bl
#define GSMEM (3 * GSTAGE)      // 98304

__device__ __forceinline__ void gemm_core(
    const __nv_bfloat16* __restrict__ Ah, const __nv_bfloat16* __restrict__ Al,
    const __nv_bfloat16* __restrict__ Bh, const __nv_bfloat16* __restrict__ Bl,
    char* sm, float acc[2][8][4], int m0, int n0) {
    uint32_t sb = smem_u32(sm);
    int tid = threadIdx.x;
    int lane = tid & 31;
    int wid = tid >> 5;
    int warp_m = wid & 3;
    int warp_n = wid >> 2;

    const __nv_bfloat16* gsrc[4] = {
        Ah + (size_t)m0 * D_, Al + (size_t)m0 * D_,
        Bh + (size_t)n0 * D_, Bl + (size_t)n0 * D_};

    int ldrow = tid >> 2;  // 0..63
    int ldc16 = tid & 3;   // 16B chunk in 64B row

    auto load_stage = [&](int c) {
        uint32_t dbase = sb + (c % 3) * GSTAGE;
#pragma unroll
        for (int op = 0; op < 4; op++) {
#pragma unroll
            for (int i = 0; i < 2; i++) {
                int row = ldrow + i * 64;
                uint32_t dst = dbase + op * GTILE + swz64(row, ldc16);
                const __nv_bfloat16* src =
                    gsrc[op] + (size_t)row * D_ + c * 32 + ldc16 * 8;
                CP16(dst, src);
            }
        }
        CP_COMMIT();
    };

    load_stage(0);
    load_stage(1);

#pragma unroll
    for (int mt = 0; mt < 2; mt++)
#pragma unroll
        for (int nt = 0; nt < 8; nt++)
#pragma unroll
            for (int r = 0; r < 4; r++) acc[mt][nt][r] = 0.0f;

    for (int c = 0; c < NCHUNK; c++) {
        if (c < NCHUNK - 1) CP_WAIT1(); else CP_WAIT0();
        __syncthreads();
        if (c + 2 < NCHUNK) load_stage(c + 2);
        uint32_t base = sb + (c % 3) * GSTAGE;

#pragma unroll
        for (int s = 0; s < 2; s++) {
            uint32_t ah[2][4], al[2][4];
#pragma unroll
            for (int mt = 0; mt < 2; mt++) {
                uint32_t arow = warp_m * 32 + mt * 16 + (lane & 15);
                uint32_t aoff = swz64(arow, 2 * s + (lane >> 4));
                LDSM_X4(ah[mt], base + aoff);
                LDSM_X4(al[mt], base + GTILE + aoff);
            }
            uint32_t bh[4][4], bl[4][4];
#pragma unroll
            for (int p = 0; p < 4; p++) {
                uint32_t brow = warp_n * 64 + p * 16 + ((lane >> 4) << 3) + (lane & 7);
                uint32_t boff = swz64(brow, 2 * s + ((lane >> 3) & 1));
                LDSM_X4(bh[p], base + 2 * GTILE + boff);
                LDSM_X4(bl[p], base + 3 * GTILE + boff);
            }
#pragma unroll
            for (int mt = 0; mt < 2; mt++)
#pragma unroll
                for (int nt = 0; nt < 8; nt++) {
                    int p = nt >> 1, hf = (nt & 1) * 2;
                    MMA_BF16(acc[mt][nt], ah[mt], bh[p][hf], bh[p][hf + 1]);
                    MMA_BF16(acc[mt][nt], ah[mt], bl[p][hf], bl[p][hf + 1]);
                    MMA_BF16(acc[mt][nt], al[mt], bh[p][hf], bh[p][hf + 1]);
                }
        }
    }
}

__global__ void __launch_bounds__(256, 2) gemm_qkv(
    const __nv_bfloat16* __restrict__ Xh, const __nv_bfloat16* __restrict__ Xl) {
    extern __shared__ char sm[];
    int z = blockIdx.z;
    int m0 = blockIdx.y * 128;
    int n0 = blockIdx.x * 128;

    float acc[2][8][4];
    gemm_core(Xh, Xl, g_wh[z], g_wl[z], sm, acc, m0, n0);

    int lane = threadIdx.x & 31;
    int wid = threadIdx.x >> 5;
    int warp_m = wid & 3;
    int warp_n = wid >> 2;
    const float QSCALE = 0.125f * 1.4426950408889634f;

#pragma unroll
    for (int mt = 0; mt < 2; mt++)
#pragma unroll
        for (int nt = 0; nt < 8; nt++)
#pragma unroll
            for (int half = 0; half < 2; half++) {
                int m = m0 + warp_m * 32 + mt * 16 + (lane >> 2) + half * 8;
                int n = n0 + warp_n * 64 + nt * 8 + (lane & 3) * 2;
                float v0 = acc[mt][nt][half * 2];
                float v1 = acc[mt][nt][half * 2 + 1];
                int b = m >> 11, s = m & (S_ - 1), h = n >> 6, d = n & 63;
                size_t off = ((((size_t)b * H_ + h) * S_ + s) << 6) + d;
                if (z == 2) {
                    *(float2*)&g_v[off] = make_float2(v0, v1);
                } else {
                    float2 sc = g_sc[(s << 5) | (d >> 1)];  // d even
                    float y0 = v0 * sc.y - v1 * sc.x;
                    float y1 = v0 * sc.x + v1 * sc.y;
                    if (z == 0) {
                        y0 *= QSCALE; y1 *= QSCALE;
                        store_split2(g_qh, g_ql, off, y0, y1);
                    } else {
                        store_split2(g_kh, g_kl, off, y0, y1);
                    }
                }
            }
}

// Wo GEMM: attn(bf16 split) @ Wo^T -> f32 out (plain layout)
__global__ void __launch_bounds__(256, 2) gemm_out(float* __restrict__ C) {
    extern __shared__ char sm[];
    int m0 = blockIdx.y * 128;
    int n0 = blockIdx.x * 128;
    float acc[2][8][4];
    gemm_core(g_ah, g_al, g_wh[3], g_wl[3], sm, acc, m0, n0);

    int lane = threadIdx.x & 31;
    int wid = threadIdx.x >> 5;
    int warp_m = wid & 3;
    int warp_n = wid >> 2;
#pragma unroll
    for (int mt = 0; mt < 2; mt++)
#pragma unroll
        for (int nt = 0; nt < 8; nt++)
#pragma unroll
            for (int half = 0; half < 2; half++) {
                int m = m0 + warp_m * 32 + mt * 16 + (lane >> 2) + half * 8;
                int n = n0 + warp_n * 64 + nt * 8 + (lane & 3) * 2;
                *(float2*)&C[(size_t)m * D_ + n] =
                    make_float2(acc[mt][nt][half * 2], acc[mt][nt][half * 2 + 1]);
            }
}

// ---------------------------------------------------------------------------
// V: split + transpose to [B,H,64,S], fp16 hi/lo (P·V runs in fp16)
// ---------------------------------------------------------------------------
__global__ void __launch_bounds__(256) vsplit_t_kernel(
    const float* __restrict__ V, __half* __restrict__ Vth,
    __half* __restrict__ Vtl) {
    __shared__ float t[64][65];
    int bh = blockIdx.y;
    int s0 = blockIdx.x * 64;
    int tid = threadIdx.x;
#pragma unroll
    for (int i = 0; i < 16; i++) {
        int e = tid + i * 256;
        int s = e >> 6, d = e & 63;
        t[d][s] = V[((size_t)bh * S_ + s0 + s) * 64 + d];
    }
    __syncthreads();
#pragma unroll
    for (int i = 0; i < 16; i++) {
        int e = tid + i * 256;
        int d = e >> 6, sj = e & 63;
        float val = t[d][sj];
        __half h = __float2half_rn(val);
        size_t o = ((size_t)bh * 64 + d) * S_ + s0 + sj;
        Vth[o] = h;
        Vtl[o] = __float2half_rn(val - __half2float(h));
    }
}

// ---------------------------------------------------------------------------
// Tensor-core causal flash attention.
// QK: bf16 3-pass (hi/lo split). PV: fp16, P single + V hi/lo = 2 passes.
// Skip-rescale softmax. Q fragments hoisted to registers.
// ---------------------------------------------------------------------------
#define AST 144
#define AQ_B (128 * AST)
#define AKV_TILE (64 * AST)
#define AKV_STAGE (4 * AKV_TILE)
#define A_OST (2 * AQ_B)
#define ASMEM (A_OST + 2 * AKV_STAGE)

__global__ void __launch_bounds__(128, 2) attn_mma(
    const __nv_bfloat16* __restrict__ Qh, const __nv_bfloat16* __restrict__ Ql,
    const __nv_bfloat16* __restrict__ Kh, const __nv_bfloat16* __restrict__ Kl,
    const __half* __restrict__ Vth, const __half* __restrict__ Vtl,
    __nv_bfloat16* __restrict__ Oh, __nv_bfloat16* __restrict__ Ol) {
    extern __shared__ char sm[];
    uint32_t sb = smem_u32(sm);
    int tid = threadIdx.x;
    int lane = tid & 31;
    int wm = tid >> 5;
    int bh = blockIdx.y;
    int qtile = gridDim.x - 1 - blockIdx.x;  // heavy tiles first
    int q0 = qtile * 128;
    size_t bhS = (size_t)bh * S_;
    int g = lane >> 2, t4 = lane & 3;

    // Q copy (group 0)
    {
        const __nv_bfloat16* sh = Qh + (bhS + q0 + tid) * 64;
        const __nv_bfloat16* sl = Ql + (bhS + q0 + tid) * 64;
        uint32_t dh = sb + tid * AST;
        uint32_t dl = sb + AQ_B + tid * AST;
#pragma unroll
        for (int c = 0; c < 8; c++) {
            CP16(dh + c * 16, sh + c * 8);
            CP16(dl + c * 16, sl + c * 8);
        }
        CP_COMMIT();
    }

    int nblocks = qtile * 2 + 2;

    int krow = tid >> 1;
    int hc = (tid & 1) * 4;
    auto load_kv = [&](int c) {
        uint32_t base = sb + A_OST + (c & 1) * AKV_STAGE;
        int kb = c * 64;
        const __nv_bfloat16* skh = Kh + (bhS + kb + krow) * 64 + hc * 8;
        const __nv_bfloat16* skl = Kl + (bhS + kb + krow) * 64 + hc * 8;
        const __half* svh = Vth + ((size_t)bh * 64 + krow) * S_ + kb + hc * 8;
        const __half* svl = Vtl + ((size_t)bh * 64 + krow) * S_ + kb + hc * 8;
        uint32_t d0 = base + krow * AST + hc * 16;
#pragma unroll
        for (int i = 0; i < 4; i++) {
            CP16(d0 + i * 16, skh + i * 8);
            CP16(d0 + AKV_TILE + i * 16, skl + i * 8);
            CP16(d0 + 2 * AKV_TILE + i * 16, svh + i * 8);
            CP16(d0 + 3 * AKV_TILE + i * 16, svl + i * 8);
        }
        CP_COMMIT();
    };
    load_kv(0);   // group 1
    load_kv(1);   // group 2

    // Q fragments -> registers, once
    CP_WAIT2();
    __syncthreads();
    uint32_t qfh[2][4][4], qfl[2][4][4];
#pragma unroll
    for (int mt = 0; mt < 2; mt++)
#pragma unroll
        for (int ks = 0; ks < 4; ks++) {
            uint32_t qa = sb + (wm * 32 + mt * 16 + (lane & 15)) * AST +
                          ks * 32 + ((lane >> 4) << 4);
            LDSM_X4(qfh[mt][ks], qa);
            LDSM_X4(qfl[mt][ks], qa + AQ_B);
        }

    float o[2][8][4];
    float Sv[2][8][4];
    float mr[2][2], lr[2][2];
#pragma unroll
    for (int mt = 0; mt < 2; mt++) {
#pragma unroll
        for (int nt = 0; nt < 8; nt++)
#pragma unroll
            for (int r = 0; r < 4; r++) o[mt][nt][r] = 0.0f;
        mr[mt][0] = mr[mt][1] = -INFINITY;
        lr[mt][0] = lr[mt][1] = 0.0f;
    }

    for (int c = 0; c < nblocks; c++) {
        if (c == nblocks - 1) CP_WAIT0(); else CP_WAIT1();
        __syncthreads();
        uint32_t base = sb + A_OST + (c & 1) * AKV_STAGE;
        int kb = c * 64;

#pragma unroll
        for (int mt = 0; mt < 2; mt++)
#pragma unroll
            for (int nt = 0; nt < 8; nt++)
#pragma unroll
                for (int r = 0; r < 4; r++) Sv[mt][nt][r] = 0.0f;

        // ---- S = Q K^T (bf16 3-pass) ----
#pragma unroll
        for (int ks = 0; ks < 4; ks++) {
#pragma unroll
            for (int ntp = 0; ntp < 4; ntp++) {
                uint32_t ba = base +
                    (ntp * 16 + ((lane >> 4) << 3) + (lane & 7)) * AST +
                    ks * 32 + (((lane >> 3) & 1) << 4);
                uint32_t bhf[4], blf[4];
                LDSM_X4(bhf, ba);
                LDSM_X4(blf, ba + AKV_TILE);
#pragma unroll
                for (int mt = 0; mt < 2; mt++)
#pragma unroll
                    for (int sub = 0; sub < 2; sub++) {
                        int nt = ntp * 2 + sub;
                        MMA_BF16(Sv[mt][nt], qfh[mt][ks], bhf[sub * 2], bhf[sub * 2 + 1]);
                        MMA_BF16(Sv[mt][nt], qfh[mt][ks], blf[sub * 2], blf[sub * 2 + 1]);
                        MMA_BF16(Sv[mt][nt], qfl[mt][ks], bhf[sub * 2], bhf[sub * 2 + 1]);
                    }
            }
        }

        // ---- causal mask ----
        if (kb + 63 > q0 + wm * 32) {
#pragma unroll
            for (int mt = 0; mt < 2; mt++)
#pragma unroll
                for (int nt = 0; nt < 8; nt++)
#pragma unroll
                    for (int r = 0; r < 4; r++) {
                        int col = kb + nt * 8 + t4 * 2 + (r & 1);
                        int row = q0 + wm * 32 + mt * 16 + g + (r >> 1) * 8;
                        if (col > row) Sv[mt][nt][r] = -INFINITY;
                    }
        }

        // ---- online softmax (skip rescale when max unchanged) ----
#pragma unroll
        for (int mt = 0; mt < 2; mt++)
#pragma unroll
            for (int h = 0; h < 2; h++) {
                float mx = Sv[mt][0][2 * h];
#pragma unroll
                for (int nt = 0; nt < 8; nt++) {
                    mx = fmaxf(mx, Sv[mt][nt][2 * h]);
                    mx = fmaxf(mx, Sv[mt][nt][2 * h + 1]);
                }
                mx = fmaxf(mx, __shfl_xor_sync(0xffffffff, mx, 1));
                mx = fmaxf(mx, __shfl_xor_sync(0xffffffff, mx, 2));
                if (mx > mr[mt][h]) {
                    float alpha = exp2p(mr[mt][h] - mx);
                    mr[mt][h] = mx;
                    lr[mt][h] *= alpha;
#pragma unroll
                    for (int nt = 0; nt < 8; nt++) {
                        o[mt][nt][2 * h] *= alpha;
                        o[mt][nt][2 * h + 1] *= alpha;
                    }
                }
                float mn = mr[mt][h];
                float ps = 0.0f;
#pragma unroll
                for (int nt = 0; nt < 8; nt++) {
                    float p0 = exp2p(Sv[mt][nt][2 * h] - mn);
                    float p1 = exp2p(Sv[mt][nt][2 * h + 1] - mn);
                    Sv[mt][nt][2 * h] = p0;
                    Sv[mt][nt][2 * h + 1] = p1;
                    ps += p0 + p1;
                }
                ps += __shfl_xor_sync(0xffffffff, ps, 1);
                ps += __shfl_xor_sync(0xffffffff, ps, 2);
                lr[mt][h] += ps;
            }

        // ---- O += P V (fp16: P single, V hi/lo -> 2 passes) ----
#pragma unroll
        for (int ks = 0; ks < 4; ks++) {
            uint32_t ph[2][4];
#pragma unroll
            for (int mt = 0; mt < 2; mt++)
#pragma unroll
                for (int u = 0; u < 4; u++) {
                    int nt = 2 * ks + (u >> 1);
                    int r0 = (u & 1) * 2;
                    __half2 hh = __floats2half2_rn(Sv[mt][nt][r0],
                                                   Sv[mt][nt][r0 + 1]);
                    ph[mt][u] = *(uint32_t*)&hh;
                }
#pragma unroll
            for (int ntp = 0; ntp < 4; ntp++) {
                uint32_t va = base + 2 * AKV_TILE +
                    (ntp * 16 + ((lane >> 4) << 3) + (lane & 7)) * AST +
                    ks * 32 + (((lane >> 3) & 1) << 4);
                uint32_t bvh[4], bvl[4];
                LDSM_X4(bvh, va);
                LDSM_X4(bvl, va + AKV_TILE);
#pragma unroll
                for (int mt = 0; mt < 2; mt++)
#pragma unroll
                    for (int sub = 0; sub < 2; sub++) {
                        int nt = ntp * 2 + sub;
                        MMA_FP16(o[mt][nt], ph[mt], bvh[sub * 2], bvh[sub * 2 + 1]);
                        MMA_FP16(o[mt][nt], ph[mt], bvl[sub * 2], bvl[sub * 2 + 1]);
                    }
            }
        }

        __syncthreads();
        if (c + 2 < nblocks) load_kv(c + 2);
    }

    // Epilogue: normalize + bf16 hi/lo split write to [B,S,H,64]
    int b = bh >> 4, hh = bh & 15;
#pragma unroll
    for (int mt = 0; mt < 2; mt++)
#pragma unroll
        for (int h = 0; h < 2; h++) {
            float inv = 1.0f / lr[mt][h];
            int row = q0 + wm * 32 + mt * 16 + g + 8 * h;
#pragma unroll
            for (int nt = 0; nt < 8; nt++) {
                int d = nt * 8 + t4 * 2;
                size_t off = (((size_t)b * S_ + row) * H_ + hh) * 64 + d;
                store_split2(Oh, Ol, off, o[mt][nt][2 * h] * inv,
                             o[mt][nt][2 * h + 1] * inv);
            }
        }
}

// ---------------------------------------------------------------------------
// Launch
// ---------------------------------------------------------------------------
extern "C" void kernel_launch(void* const* d_in, const int* in_sizes, int n_in,
                              void* d_out, int out_size) {
    const float* x = (const float*)d_in[0];
    const float* Wq = (const float*)d_in[1];
    const float* Wk = (const float*)d_in[2];
    const float* Wv = (const float*)d_in[3];
    const float* Wo = (const float*)d_in[4];
    const int* pos = (const int*)d_in[5];

    float* v;
    __nv_bfloat16 *xh, *xl, *ah, *al, *wh, *wl;
    __nv_bfloat16 *qh, *ql, *kh, *kl;
    __half *vth, *vtl;
    cudaGetSymbolAddress((void**)&v, g_v);
    cudaGetSymbolAddress((void**)&xh, g_xh);
    cudaGetSymbolAddress((void**)&xl, g_xl);
    cudaGetSymbolAddress((void**)&ah, g_ah);
    cudaGetSymbolAddress((void**)&al, g_al);
    cudaGetSymbolAddress((void**)&wh, g_wh);
    cudaGetSymbolAddress((void**)&wl, g_wl);
    cudaGetSymbolAddress((void**)&qh, g_qh);
    cudaGetSymbolAddress((void**)&ql, g_ql);
    cudaGetSymbolAddress((void**)&kh, g_kh);
    cudaGetSymbolAddress((void**)&kl, g_kl);
    cudaGetSymbolAddress((void**)&vth, g_vth);
    cudaGetSymbolAddress((void**)&vtl, g_vtl);

    cudaFuncSetAttribute(gemm_qkv,
                         cudaFuncAttributeMaxDynamicSharedMemorySize, GSMEM);
    cudaFuncSetAttribute(gemm_out,
                         cudaFuncAttributeMaxDynamicSharedMemorySize, GSMEM);
    cudaFuncSetAttribute(attn_mma,
                         cudaFuncAttributeMaxDynamicSharedMemorySize, ASMEM);

    sincos_table_kernel<<<(S_ * 32) / 256, 256>>>(pos);

    const int NX = B_ * S_ * D_;  // 4M
    split_kernel<<<NX / 256, 256>>>(x, xh, xl, NX);
    split4_kernel<<<(4 * D_ * D_) / 256, 256>>>(Wq, Wk, Wv, Wo, wh, wl);

    gemm_qkv<<<dim3(D_ / 128, (B_ * S_) / 128, 3), 256, GSMEM>>>(xh, xl);

    vsplit_t_kernel<<<dim3(S_ / 64, B_ * H_), 256>>>(v, vth, vtl);

    attn_mma<<<dim3(S_ / 128, B_ * H_), 128, ASMEM>>>(qh, ql, kh, kl, vth, vtl,
                                                      ah, al);

    gemm_out<<<dim3(D_ / 128, (B_ * S_) / 128), 256, GSMEM>>>((float*)d_out);
}

// round 16
// speedup vs baseline: 2.0581x; 1.0891x over previous
#include <cuda_runtime.h>
#include <cuda_bf16.h>
#include <cuda_fp16.h>
#include <math.h>
#include <cstdint>

// Problem constants
#define B_ 2
#define S_ 2048
#define D_ 1024
#define H_ 16
#define DK_ 64

// ---------------------------------------------------------------------------
// Scratch (__device__ globals; no allocation allowed)
// ---------------------------------------------------------------------------
__device__ float2 g_sc[S_ * 32];

// bf16 split buffers
__device__ __nv_bfloat16 g_xh[B_ * S_ * D_];
__device__ __nv_bfloat16 g_xl[B_ * S_ * D_];
__device__ __nv_bfloat16 g_ah[B_ * S_ * D_];   // attn out hi [B,S,H,64]
__device__ __nv_bfloat16 g_al[B_ * S_ * D_];
__device__ __nv_bfloat16 g_wh[4][D_ * D_];
__device__ __nv_bfloat16 g_wl[4][D_ * D_];

__device__ __nv_bfloat16 g_qh[B_ * S_ * D_];   // [B,H,S,64], rope+scaled
__device__ __nv_bfloat16 g_ql[B_ * S_ * D_];
__device__ __nv_bfloat16 g_kh[B_ * S_ * D_];   // [B,H,S,64], rope
__device__ __nv_bfloat16 g_kl[B_ * S_ * D_];
__device__ __half g_vth[B_ * S_ * D_];         // [B,H,64,S] fp16 (single)

// ---------------------------------------------------------------------------
// PTX helpers (baseline ISA: mma.sync / ldmatrix / cp.async — sm_103-safe)
// ---------------------------------------------------------------------------
__device__ __forceinline__ uint32_t smem_u32(const void* p) {
    uint32_t a;
    asm("{ .reg .u64 t; cvta.to.shared.u64 t, %1; cvt.u32.u64 %0, t; }"
        : "=r"(a) : "l"(p));
    return a;
}

#define CP16(dst, src) \
    asm volatile("cp.async.cg.shared.global [%0], [%1], 16;" \
                 :: "r"(dst), "l"(src))
#define CP_COMMIT() asm volatile("cp.async.commit_group;")
#define CP_WAIT2() asm volatile("cp.async.wait_group 2;")
#define CP_WAIT1() asm volatile("cp.async.wait_group 1;")
#define CP_WAIT0() asm volatile("cp.async.wait_group 0;")

#define LDSM_X4(r, a)                                                       \
    asm volatile("ldmatrix.sync.aligned.m8n8.x4.shared.b16 "                \
                 "{%0,%1,%2,%3}, [%4];"                                     \
                 : "=r"((r)[0]), "=r"((r)[1]), "=r"((r)[2]), "=r"((r)[3])   \
                 : "r"(a))

#define MMA_BF16(d, a, b0, b1)                                              \
    asm volatile("mma.sync.aligned.m16n8k16.row.col.f32.bf16.bf16.f32 "     \
                 "{%0,%1,%2,%3},{%4,%5,%6,%7},{%8,%9},{%0,%1,%2,%3};"       \
                 : "+f"((d)[0]), "+f"((d)[1]), "+f"((d)[2]), "+f"((d)[3])   \
                 : "r"((a)[0]), "r"((a)[1]), "r"((a)[2]), "r"((a)[3]),      \
                   "r"(b0), "r"(b1))

#define MMA_FP16(d, a, b0, b1)                                              \
    asm volatile("mma.sync.aligned.m16n8k16.row.col.f32.f16.f16.f32 "      \
                 "{%0,%1,%2,%3},{%4,%5,%6,%7},{%8,%9},{%0,%1,%2,%3};"       \
                 : "+f"((d)[0]), "+f"((d)[1]), "+f"((d)[2]), "+f"((d)[3])   \
                 : "r"((a)[0]), "r"((a)[1]), "r"((a)[2]), "r"((a)[3]),      \
                   "r"(b0), "r"(b1))

// FFMA-only exp2 for t <= 0 (deg-6 poly, rel err ~1.2e-7)
__device__ __forceinline__ float exp2p(float t) {
    t = fmaxf(t, -80.0f);
    float y = __fadd_rn(t, 12582912.0f);
    int n = __float_as_int(y) - 0x4B400000;
    float f = __fsub_rn(t, __fsub_rn(y, 12582912.0f));
    float p = 1.54035304e-4f;
    p = fmaf(p, f, 1.33335581e-3f);
    p = fmaf(p, f, 9.61812911e-3f);
    p = fmaf(p, f, 5.55041087e-2f);
    p = fmaf(p, f, 2.40226507e-1f);
    p = fmaf(p, f, 6.93147181e-1f);
    p = fmaf(p, f, 1.0f);
    return __int_as_float(__float_as_int(p) + (n << 23));
}

// Write an fp32 pair as (hi, lo) bf16x2 pairs
__device__ __forceinline__ void store_split2(__nv_bfloat16* Hp,
                                             __nv_bfloat16* Lp, size_t off,
                                             float v0, float v1) {
    __nv_bfloat162 hh = __floats2bfloat162_rn(v0, v1);
    *(__nv_bfloat162*)(Hp + off) = hh;
    __nv_bfloat162 ll = __floats2bfloat162_rn(v0 - __bfloat162float(hh.x),
                                              v1 - __bfloat162float(hh.y));
    *(__nv_bfloat162*)(Lp + off) = ll;
}

// 64B-row swizzle for GEMM smem tiles: rows of 4x16B chunks.
__device__ __forceinline__ uint32_t swz64(uint32_t row, uint32_t chunk) {
    return row * 64 + ((chunk ^ ((row >> 1) & 3)) << 4);
}

// ---------------------------------------------------------------------------
// fp32 -> (hi, lo) bf16 split (x input)
// ---------------------------------------------------------------------------
__global__ void split_kernel(const float* __restrict__ in,
                             __nv_bfloat16* __restrict__ hi,
                             __nv_bfloat16* __restrict__ lo, int n) {
    int i = blockIdx.x * blockDim.x + threadIdx.x;
    if (i >= n) return;
    float v = in[i];
    __nv_bfloat16 h = __float2bfloat16(v);
    hi[i] = h;
    lo[i] = __float2bfloat16(v - __bfloat162float(h));
}

// All 4 weights in one launch (g_wh/g_wl are [4][NW] contiguous)
__global__ void split4_kernel(const float* __restrict__ w0,
                              const float* __restrict__ w1,
                              const float* __restrict__ w2,
                              const float* __restrict__ w3,
                              __nv_bfloat16* __restrict__ hi,
                              __nv_bfloat16* __restrict__ lo) {
    int i = blockIdx.x * blockDim.x + threadIdx.x;
    int sel = i >> 20;  // NW = 1<<20
    int off = i & ((1 << 20) - 1);
    const float* src = (sel == 0) ? w0 : (sel == 1) ? w1 : (sel == 2) ? w2 : w3;
    float v = src[off];
    __nv_bfloat16 h = __float2bfloat16(v);
    hi[i] = h;
    lo[i] = __float2bfloat16(v - __bfloat162float(h));
}

// ---------------------------------------------------------------------------
// sin/cos table (exact range reduction)
// ---------------------------------------------------------------------------
__global__ void sincos_table_kernel(const int* __restrict__ pos) {
    int idx = blockIdx.x * blockDim.x + threadIdx.x;
    if (idx >= S_ * 32) return;
    int s = idx >> 5;
    int p = idx & 31;
    float invf = (float)exp2(-(double)p * 0.4152410118609203);
    float ang = (float)pos[s] * invf;
    double a = (double)ang;
    double kq = floor(a * 0.15915494309189535);
    float r = (float)(a - kq * 6.283185307179586);
    float sn, cs;
    sincosf(r, &sn, &cs);
    g_sc[idx] = make_float2(sn, cs);
}

// ---------------------------------------------------------------------------
// GEMM core: 3-stage cp.async pipeline, swizzled 64B rows, 1 sync per chunk.
// ---------------------------------------------------------------------------
#define NCHUNK 32
#define GTILE 8192              // 128 rows x 64B
#define GSTAGE (4 * GTILE)      // Ah, Al, Bh, Bl
#define GSMEM (3 * GSTAGE)      // 98304

__device__ __forceinline__ void gemm_core(
    const __nv_bfloat16* __restrict__ Ah, const __nv_bfloat16* __restrict__ Al,
    const __nv_bfloat16* __restrict__ Bh, const __nv_bfloat16* __restrict__ Bl,
    char* sm, float acc[2][8][4], int m0, int n0) {
    uint32_t sb = smem_u32(sm);
    int tid = threadIdx.x;
    int lane = tid & 31;
    int wid = tid >> 5;
    int warp_m = wid & 3;
    int warp_n = wid >> 2;

    const __nv_bfloat16* gsrc[4] = {
        Ah + (size_t)m0 * D_, Al + (size_t)m0 * D_,
        Bh + (size_t)n0 * D_, Bl + (size_t)n0 * D_};

    int ldrow = tid >> 2;  // 0..63
    int ldc16 = tid & 3;   // 16B chunk in 64B row

    auto load_stage = [&](int c) {
        uint32_t dbase = sb + (c % 3) * GSTAGE;
#pragma unroll
        for (int op = 0; op < 4; op++) {
#pragma unroll
            for (int i = 0; i < 2; i++) {
                int row = ldrow + i * 64;
                uint32_t dst = dbase + op * GTILE + swz64(row, ldc16);
                const __nv_bfloat16* src =
                    gsrc[op] + (size_t)row * D_ + c * 32 + ldc16 * 8;
                CP16(dst, src);
            }
        }
        CP_COMMIT();
    };

    load_stage(0);
    load_stage(1);

#pragma unroll
    for (int mt = 0; mt < 2; mt++)
#pragma unroll
        for (int nt = 0; nt < 8; nt++)
#pragma unroll
            for (int r = 0; r < 4; r++) acc[mt][nt][r] = 0.0f;

    for (int c = 0; c < NCHUNK; c++) {
        if (c < NCHUNK - 1) CP_WAIT1(); else CP_WAIT0();
        __syncthreads();
        if (c + 2 < NCHUNK) load_stage(c + 2);
        uint32_t base = sb + (c % 3) * GSTAGE;

#pragma unroll
        for (int s = 0; s < 2; s++) {
            uint32_t ah[2][4], al[2][4];
#pragma unroll
            for (int mt = 0; mt < 2; mt++) {
                uint32_t arow = warp_m * 32 + mt * 16 + (lane & 15);
                uint32_t aoff = swz64(arow, 2 * s + (lane >> 4));
                LDSM_X4(ah[mt], base + aoff);
                LDSM_X4(al[mt], base + GTILE + aoff);
            }
            uint32_t bh[4][4], bl[4][4];
#pragma unroll
            for (int p = 0; p < 4; p++) {
                uint32_t brow = warp_n * 64 + p * 16 + ((lane >> 4) << 3) + (lane & 7);
                uint32_t boff = swz64(brow, 2 * s + ((lane >> 3) & 1));
                LDSM_X4(bh[p], base + 2 * GTILE + boff);
                LDSM_X4(bl[p], base + 3 * GTILE + boff);
            }
#pragma unroll
            for (int mt = 0; mt < 2; mt++)
#pragma unroll
                for (int nt = 0; nt < 8; nt++) {
                    int p = nt >> 1, hf = (nt & 1) * 2;
                    MMA_BF16(acc[mt][nt], ah[mt], bh[p][hf], bh[p][hf + 1]);
                    MMA_BF16(acc[mt][nt], ah[mt], bl[p][hf], bl[p][hf + 1]);
                    MMA_BF16(acc[mt][nt], al[mt], bh[p][hf], bh[p][hf + 1]);
                }
        }
    }
}

// z=0: rope(+qscale) -> qh/ql; z=1: rope -> kh/kl
// z=2: in-smem transpose -> g_vth fp16 [B,H,64,S]  (vsplit kernel fused away)
__global__ void __launch_bounds__(256, 2) gemm_qkv(
    const __nv_bfloat16* __restrict__ Xh, const __nv_bfloat16* __restrict__ Xl) {
    extern __shared__ char sm[];
    int z = blockIdx.z;
    int m0 = blockIdx.y * 128;
    int n0 = blockIdx.x * 128;

    float acc[2][8][4];
    gemm_core(Xh, Xl, g_wh[z], g_wl[z], sm, acc, m0, n0);

    int lane = threadIdx.x & 31;
    int wid = threadIdx.x >> 5;
    int warp_m = wid & 3;
    int warp_n = wid >> 2;
    const float QSCALE = 0.125f * 1.4426950408889634f;

    if (z == 2) {
        // V: transpose in smem (mainloop done with it), emit fp16 [b,h,d,s]
        __syncthreads();
        float* sT = (float*)sm;  // [128 n][130]
#pragma unroll
        for (int mt = 0; mt < 2; mt++)
#pragma unroll
            for (int nt = 0; nt < 8; nt++)
#pragma unroll
                for (int half = 0; half < 2; half++) {
                    int mm = warp_m * 32 + mt * 16 + (lane >> 2) + half * 8;
                    int nn = warp_n * 64 + nt * 8 + (lane & 3) * 2;
                    sT[nn * 130 + mm] = acc[mt][nt][half * 2];
                    sT[(nn + 1) * 130 + mm] = acc[mt][nt][half * 2 + 1];
                }
        __syncthreads();
        int nn = threadIdx.x >> 1;
        int mc = (threadIdx.x & 1) * 64;
        int b = m0 >> 11;
        int s0l = m0 & (S_ - 1);
        int h = (n0 + nn) >> 6;
        int d = (n0 + nn) & 63;
        __half* dst = g_vth + ((((size_t)b * H_ + h) * 64 + d) << 11) + s0l + mc;
        const float* srow = sT + nn * 130 + mc;
#pragma unroll
        for (int j = 0; j < 64; j += 8) {
            __half2 h0 = __floats2half2_rn(srow[j + 0], srow[j + 1]);
            __half2 h1 = __floats2half2_rn(srow[j + 2], srow[j + 3]);
            __half2 h2 = __floats2half2_rn(srow[j + 4], srow[j + 5]);
            __half2 h3 = __floats2half2_rn(srow[j + 6], srow[j + 7]);
            uint4 u = make_uint4(*(uint32_t*)&h0, *(uint32_t*)&h1,
                                 *(uint32_t*)&h2, *(uint32_t*)&h3);
            *(uint4*)(dst + j) = u;
        }
        return;
    }

#pragma unroll
    for (int mt = 0; mt < 2; mt++)
#pragma unroll
        for (int nt = 0; nt < 8; nt++)
#pragma unroll
            for (int half = 0; half < 2; half++) {
                int m = m0 + warp_m * 32 + mt * 16 + (lane >> 2) + half * 8;
                int n = n0 + warp_n * 64 + nt * 8 + (lane & 3) * 2;
                float v0 = acc[mt][nt][half * 2];
                float v1 = acc[mt][nt][half * 2 + 1];
                int b = m >> 11, s = m & (S_ - 1), h = n >> 6, d = n & 63;
                size_t off = ((((size_t)b * H_ + h) * S_ + s) << 6) + d;
                float2 sc = g_sc[(s << 5) | (d >> 1)];  // d even
                float y0 = v0 * sc.y - v1 * sc.x;
                float y1 = v0 * sc.x + v1 * sc.y;
                if (z == 0) {
                    y0 *= QSCALE; y1 *= QSCALE;
                    store_split2(g_qh, g_ql, off, y0, y1);
                } else {
                    store_split2(g_kh, g_kl, off, y0, y1);
                }
            }
}

// Wo GEMM: attn(bf16 split) @ Wo^T -> f32 out (plain layout)
__global__ void __launch_bounds__(256, 2) gemm_out(float* __restrict__ C) {
    extern __shared__ char sm[];
    int m0 = blockIdx.y * 128;
    int n0 = blockIdx.x * 128;
    float acc[2][8][4];
    gemm_core(g_ah, g_al, g_wh[3], g_wl[3], sm, acc, m0, n0);

    int lane = threadIdx.x & 31;
    int wid = threadIdx.x >> 5;
    int warp_m = wid & 3;
    int warp_n = wid >> 2;
#pragma unroll
    for (int mt = 0; mt < 2; mt++)
#pragma unroll
        for (int nt = 0; nt < 8; nt++)
#pragma unroll
            for (int half = 0; half < 2; half++) {
                int m = m0 + warp_m * 32 + mt * 16 + (lane >> 2) + half * 8;
                int n = n0 + warp_n * 64 + nt * 8 + (lane & 3) * 2;
                *(float2*)&C[(size_t)m * D_ + n] =
                    make_float2(acc[mt][nt][half * 2], acc[mt][nt][half * 2 + 1]);
            }
}

// ---------------------------------------------------------------------------
// Tensor-core causal flash attention.
// QK: bf16 3-pass. PV: fp16 single-pass (P and V both single fp16 — the
// P-fp16 noise already dominates; V-fp16 adds the same independent 2^-11).
// Skip-rescale softmax; Q fragments hoisted to registers.
// ---------------------------------------------------------------------------
#define AST 144
#define AQ_B (128 * AST)
#define AKV_TILE (64 * AST)
#define AKV_STAGE (3 * AKV_TILE)      // Kh, Kl, Vh
#define A_OST (2 * AQ_B)
#define ASMEM (A_OST + 2 * AKV_STAGE) // 92160

__global__ void __launch_bounds__(128, 2) attn_mma(
    const __nv_bfloat16* __restrict__ Qh, const __nv_bfloat16* __restrict__ Ql,
    const __nv_bfloat16* __restrict__ Kh, const __nv_bfloat16* __restrict__ Kl,
    const __half* __restrict__ Vth,
    __nv_bfloat16* __restrict__ Oh, __nv_bfloat16* __restrict__ Ol) {
    extern __shared__ char sm[];
    uint32_t sb = smem_u32(sm);
    int tid = threadIdx.x;
    int lane = tid & 31;
    int wm = tid >> 5;
    int bh = blockIdx.y;
    int qtile = gridDim.x - 1 - blockIdx.x;  // heavy tiles first
    int q0 = qtile * 128;
    size_t bhS = (size_t)bh * S_;
    int g = lane >> 2, t4 = lane & 3;

    // Q copy (group 0)
    {
        const __nv_bfloat16* sh = Qh + (bhS + q0 + tid) * 64;
        const __nv_bfloat16* sl = Ql + (bhS + q0 + tid) * 64;
        uint32_t dh = sb + tid * AST;
        uint32_t dl = sb + AQ_B + tid * AST;
#pragma unroll
        for (int c = 0; c < 8; c++) {
            CP16(dh + c * 16, sh + c * 8);
            CP16(dl + c * 16, sl + c * 8);
        }
        CP_COMMIT();
    }

    int nblocks = qtile * 2 + 2;

    int krow = tid >> 1;
    int hc = (tid & 1) * 4;
    auto load_kv = [&](int c) {
        uint32_t base = sb + A_OST + (c & 1) * AKV_STAGE;
        int kb = c * 64;
        const __nv_bfloat16* skh = Kh + (bhS + kb + krow) * 64 + hc * 8;
        const __nv_bfloat16* skl = Kl + (bhS + kb + krow) * 64 + hc * 8;
        const __half* svh = Vth + ((size_t)bh * 64 + krow) * S_ + kb + hc * 8;
        uint32_t d0 = base + krow * AST + hc * 16;
#pragma unroll
        for (int i = 0; i < 4; i++) {
            CP16(d0 + i * 16, skh + i * 8);
            CP16(d0 + AKV_TILE + i * 16, skl + i * 8);
            CP16(d0 + 2 * AKV_TILE + i * 16, svh + i * 8);
        }
        CP_COMMIT();
    };
    load_kv(0);   // group 1
    load_kv(1);   // group 2

    // Q fragments -> registers, once
    CP_WAIT2();
    __syncthreads();
    uint32_t qfh[2][4][4], qfl[2][4][4];
#pragma unroll
    for (int mt = 0; mt < 2; mt++)
#pragma unroll
        for (int ks = 0; ks < 4; ks++) {
            uint32_t qa = sb + (wm * 32 + mt * 16 + (lane & 15)) * AST +
                          ks * 32 + ((lane >> 4) << 4);
            LDSM_X4(qfh[mt][ks], qa);
            LDSM_X4(qfl[mt][ks], qa + AQ_B);
        }

    float o[2][8][4];
    float Sv[2][8][4];
    float mr[2][2], lr[2][2];
#pragma unroll
    for (int mt = 0; mt < 2; mt++) {
#pragma unroll
        for (int nt = 0; nt < 8; nt++)
#pragma unroll
            for (int r = 0; r < 4; r++) o[mt][nt][r] = 0.0f;
        mr[mt][0] = mr[mt][1] = -INFINITY;
        lr[mt][0] = lr[mt][1] = 0.0f;
    }

    for (int c = 0; c < nblocks; c++) {
        if (c == nblocks - 1) CP_WAIT0(); else CP_WAIT1();
        __syncthreads();
        uint32_t base = sb + A_OST + (c & 1) * AKV_STAGE;
        int kb = c * 64;

#pragma unroll
        for (int mt = 0; mt < 2; mt++)
#pragma unroll
            for (int nt = 0; nt < 8; nt++)
#pragma unroll
                for (int r = 0; r < 4; r++) Sv[mt][nt][r] = 0.0f;

        // ---- S = Q K^T (bf16 3-pass) ----
#pragma unroll
        for (int ks = 0; ks < 4; ks++) {
#pragma unroll
            for (int ntp = 0; ntp < 4; ntp++) {
                uint32_t ba = base +
                    (ntp * 16 + ((lane >> 4) << 3) + (lane & 7)) * AST +
                    ks * 32 + (((lane >> 3) & 1) << 4);
                uint32_t bhf[4], blf[4];
                LDSM_X4(bhf, ba);
                LDSM_X4(blf, ba + AKV_TILE);
#pragma unroll
                for (int mt = 0; mt < 2; mt++)
#pragma unroll
                    for (int sub = 0; sub < 2; sub++) {
                        int nt = ntp * 2 + sub;
                        MMA_BF16(Sv[mt][nt], qfh[mt][ks], bhf[sub * 2], bhf[sub * 2 + 1]);
                        MMA_BF16(Sv[mt][nt], qfh[mt][ks], blf[sub * 2], blf[sub * 2 + 1]);
                        MMA_BF16(Sv[mt][nt], qfl[mt][ks], bhf[sub * 2], bhf[sub * 2 + 1]);
                    }
            }
        }

        // ---- causal mask ----
        if (kb + 63 > q0 + wm * 32) {
#pragma unroll
            for (int mt = 0; mt < 2; mt++)
#pragma unroll
                for (int nt = 0; nt < 8; nt++)
#pragma unroll
                    for (int r = 0; r < 4; r++) {
                        int col = kb + nt * 8 + t4 * 2 + (r & 1);
                        int row = q0 + wm * 32 + mt * 16 + g + (r >> 1) * 8;
                        if (col > row) Sv[mt][nt][r] = -INFINITY;
                    }
        }

        // ---- online softmax (skip rescale when max unchanged) ----
#pragma unroll
        for (int mt = 0; mt < 2; mt++)
#pragma unroll
            for (int h = 0; h < 2; h++) {
                float mx = Sv[mt][0][2 * h];
#pragma unroll
                for (int nt = 0; nt < 8; nt++) {
                    mx = fmaxf(mx, Sv[mt][nt][2 * h]);
                    mx = fmaxf(mx, Sv[mt][nt][2 * h + 1]);
                }
                mx = fmaxf(mx, __shfl_xor_sync(0xffffffff, mx, 1));
                mx = fmaxf(mx, __shfl_xor_sync(0xffffffff, mx, 2));
                if (mx > mr[mt][h]) {
                    float alpha = exp2p(mr[mt][h] - mx);
                    mr[mt][h] = mx;
                    lr[mt][h] *= alpha;
#pragma unroll
                    for (int nt = 0; nt < 8; nt++) {
                        o[mt][nt][2 * h] *= alpha;
                        o[mt][nt][2 * h + 1] *= alpha;
                    }
                }
                float mn = mr[mt][h];
                float ps = 0.0f;
#pragma unroll
                for (int nt = 0; nt < 8; nt++) {
                    float p0 = exp2p(Sv[mt][nt][2 * h] - mn);
                    float p1 = exp2p(Sv[mt][nt][2 * h + 1] - mn);
                    Sv[mt][nt][2 * h] = p0;
                    Sv[mt][nt][2 * h + 1] = p1;
                    ps += p0 + p1;
                }
                ps += __shfl_xor_sync(0xffffffff, ps, 1);
                ps += __shfl_xor_sync(0xffffffff, ps, 2);
                lr[mt][h] += ps;
            }

        // ---- O += P V (fp16 single pass) ----
#pragma unroll
        for (int ks = 0; ks < 4; ks++) {
            uint32_t ph[2][4];
#pragma unroll
            for (int mt = 0; mt < 2; mt++)
#pragma unroll
                for (int u = 0; u < 4; u++) {
                    int nt = 2 * ks + (u >> 1);
                    int r0 = (u & 1) * 2;
                    __half2 hh = __floats2half2_rn(Sv[mt][nt][r0],
                                                   Sv[mt][nt][r0 + 1]);
                    ph[mt][u] = *(uint32_t*)&hh;
                }
#pragma unroll
            for (int ntp = 0; ntp < 4; ntp++) {
                uint32_t va = base + 2 * AKV_TILE +
                    (ntp * 16 + ((lane >> 4) << 3) + (lane & 7)) * AST +
                    ks * 32 + (((lane >> 3) & 1) << 4);
                uint32_t bvh[4];
                LDSM_X4(bvh, va);
#pragma unroll
                for (int mt = 0; mt < 2; mt++)
#pragma unroll
                    for (int sub = 0; sub < 2; sub++) {
                        int nt = ntp * 2 + sub;
                        MMA_FP16(o[mt][nt], ph[mt], bvh[sub * 2], bvh[sub * 2 + 1]);
                    }
            }
        }

        __syncthreads();
        if (c + 2 < nblocks) load_kv(c + 2);
    }

    // Epilogue: normalize + bf16 hi/lo split write to [B,S,H,64]
    int b = bh >> 4, hh = bh & 15;
#pragma unroll
    for (int mt = 0; mt < 2; mt++)
#pragma unroll
        for (int h = 0; h < 2; h++) {
            float inv = 1.0f / lr[mt][h];
            int row = q0 + wm * 32 + mt * 16 + g + 8 * h;
#pragma unroll
            for (int nt = 0; nt < 8; nt++) {
                int d = nt * 8 + t4 * 2;
                size_t off = (((size_t)b * S_ + row) * H_ + hh) * 64 + d;
                store_split2(Oh, Ol, off, o[mt][nt][2 * h] * inv,
                             o[mt][nt][2 * h + 1] * inv);
            }
        }
}

// ---------------------------------------------------------------------------
// Launch
// ---------------------------------------------------------------------------
extern "C" void kernel_launch(void* const* d_in, const int* in_sizes, int n_in,
                              void* d_out, int out_size) {
    const float* x = (const float*)d_in[0];
    const float* Wq = (const float*)d_in[1];
    const float* Wk = (const float*)d_in[2];
    const float* Wv = (const float*)d_in[3];
    const float* Wo = (const float*)d_in[4];
    const int* pos = (const int*)d_in[5];

    __nv_bfloat16 *xh, *xl, *ah, *al, *wh, *wl;
    __nv_bfloat16 *qh, *ql, *kh, *kl;
    __half* vth;
    cudaGetSymbolAddress((void**)&xh, g_xh);
    cudaGetSymbolAddress((void**)&xl, g_xl);
    cudaGetSymbolAddress((void**)&ah, g_ah);
    cudaGetSymbolAddress((void**)&al, g_al);
    cudaGetSymbolAddress((void**)&wh, g_wh);
    cudaGetSymbolAddress((void**)&wl, g_wl);
    cudaGetSymbolAddress((void**)&qh, g_qh);
    cudaGetSymbolAddress((void**)&ql, g_ql);
    cudaGetSymbolAddress((void**)&kh, g_kh);
    cudaGetSymbolAddress((void**)&kl, g_kl);
    cudaGetSymbolAddress((void**)&vth, g_vth);

    cudaFuncSetAttribute(gemm_qkv,
                         cudaFuncAttributeMaxDynamicSharedMemorySize, GSMEM);
    cudaFuncSetAttribute(gemm_out,
                         cudaFuncAttributeMaxDynamicSharedMemorySize, GSMEM);
    cudaFuncSetAttribute(attn_mma,
                         cudaFuncAttributeMaxDynamicSharedMemorySize, ASMEM);

    sincos_table_kernel<<<(S_ * 32) / 256, 256>>>(pos);

    const int NX = B_ * S_ * D_;  // 4M
    split_kernel<<<NX / 256, 256>>>(x, xh, xl, NX);
    split4_kernel<<<(4 * D_ * D_) / 256, 256>>>(Wq, Wk, Wv, Wo, wh, wl);

    gemm_qkv<<<dim3(D_ / 128, (B_ * S_) / 128, 3), 256, GSMEM>>>(xh, xl);

    attn_mma<<<dim3(S_ / 128, B_ * H_), 128, ASMEM>>>(qh, ql, kh, kl, vth,
                                                      ah, al);

    gemm_out<<<dim3(D_ / 128, (B_ * S_) / 128), 256, GSMEM>>>((float*)d_out);
}